// round 9
// baseline (speedup 1.0000x reference)
#include <cuda_runtime.h>
#include <cuda_bf16.h>
#include <math.h>
#include <stdint.h>

#define B_  256
#define T_  256
#define YD_ 6625

// ---------------- fp32 scratch ----------------
__device__ float g_sProj[256 * 512];
__device__ float g_spart[2 * 65536];
__device__ float g_gi[256 * 1536];
__device__ float g_gh[256 * 1536];

// ---------------- chunk-tiled, pre-swizzled bf16 scratch ----------------
// layout: slab(c, plane) = base + (c*2+plane)*Rpad*32 elems; row r at +r*32 elems (64B);
// within row, 16B unit j stored at (j ^ ((r>>1)&3)).
__device__ __nv_bfloat16 g_x_t [16u * 2 * 65536 * 32];
__device__ __nv_bfloat16 g_s_t [16 * 2 * 256 * 32];
__device__ __nv_bfloat16 g_cc_t[32 * 2 * 256 * 32];
__device__ __nv_bfloat16 g_h_t [16 * 2 * 256 * 32];
__device__ __nv_bfloat16 g_xe_t[16 * 2 * 512 * 32];
__device__ __nv_bfloat16 g_se_t[16 * 2 * 512 * 32];
__device__ __nv_bfloat16 g_hh_t[16 * 2 * 1536 * 32];
__device__ __nv_bfloat16 g_ih_t[32 * 2 * 1536 * 32];
__device__ __nv_bfloat16 g_fc_t[16 * 2 * 6656 * 32];

// ---------------- helpers ----------------
__device__ __forceinline__ uint32_t smem_u32(const void* p) {
    uint32_t a;
    asm("{ .reg .u64 t; cvta.to.shared.u64 t, %1; cvt.u32.u64 %0, t; }" : "=r"(a) : "l"(p));
    return a;
}
__device__ __forceinline__ void ldmx4(uint32_t addr, uint32_t* r) {
    asm volatile("ldmatrix.sync.aligned.m8n8.x4.shared.b16 {%0,%1,%2,%3}, [%4];"
        : "=r"(r[0]), "=r"(r[1]), "=r"(r[2]), "=r"(r[3]) : "r"(addr));
}
__device__ __forceinline__ void mma_bf16(float* c, const uint32_t* a, uint32_t b0, uint32_t b1) {
    asm volatile("mma.sync.aligned.m16n8k16.row.col.f32.bf16.bf16.f32 "
        "{%0,%1,%2,%3}, {%4,%5,%6,%7}, {%8,%9}, {%0,%1,%2,%3};"
        : "+f"(c[0]), "+f"(c[1]), "+f"(c[2]), "+f"(c[3])
        : "r"(a[0]), "r"(a[1]), "r"(a[2]), "r"(a[3]), "r"(b0), "r"(b1));
}
#define MBAR_INIT(mb, c) asm volatile("mbarrier.init.shared.b64 [%0], %1;" :: "r"(mb), "r"(c) : "memory")
#define MB_EXPECT(mb, n) asm volatile("mbarrier.arrive.expect_tx.shared.b64 _, [%0], %1;" :: "r"(mb), "r"(n) : "memory")
#define FENCE_ASYNC()    asm volatile("fence.proxy.async.shared::cta;" ::: "memory")
#define BULK_G2S(dst, src, sz, mb) \
    asm volatile("cp.async.bulk.shared::cluster.global.mbarrier::complete_tx::bytes [%0], [%1], %2, [%3];" \
        :: "r"(dst), "l"(src), "r"(sz), "r"(mb) : "memory")

__device__ __forceinline__ void mbar_wait(uint32_t mb, uint32_t phase) {
    asm volatile(
        "{\n\t.reg .pred P;\n\t"
        "WL%=:\n\t"
        "mbarrier.try_wait.parity.acquire.cta.shared::cta.b64 P, [%0], %1, 0x989680;\n\t"
        "@!P bra WL%=;\n\t}"
        :: "r"(mb), "r"(phase) : "memory");
}

__device__ __forceinline__ float tanh_fast(float x) {
    float xc = fminf(fmaxf(x, -15.f), 15.f);
    float e = exp2f(xc * 2.8853900817779268f);
    return __fdividef(e - 1.0f, e + 1.0f);
}
__device__ __forceinline__ uint32_t pack_hi_lo(float a, float b, uint32_t& lo) {
    __nv_bfloat16 ha = __float2bfloat16(a), hb = __float2bfloat16(b);
    __nv_bfloat16 la = __float2bfloat16(a - __bfloat162float(ha));
    __nv_bfloat16 lb = __float2bfloat16(b - __bfloat162float(hb));
    lo = (uint32_t)*(unsigned short*)&la | ((uint32_t)*(unsigned short*)&lb << 16);
    return (uint32_t)*(unsigned short*)&ha | ((uint32_t)*(unsigned short*)&hb << 16);
}

// ---------------- split writers ----------------
__device__ __forceinline__ void split_unit(const float* __restrict__ w,
                                           __nv_bfloat16* __restrict__ out,
                                           int Rpad, int K, int u)
{
    int upr = K >> 3;
    int r = u / upr, uu = u - r * upr;
    int c = uu >> 2, j = uu & 3;
    const float4* src = (const float4*)(w + (size_t)r * K + c * 32 + j * 8);
    float4 v0 = src[0], v1 = src[1];
    float f[8] = {v0.x, v0.y, v0.z, v0.w, v1.x, v1.y, v1.z, v1.w};
    uint32_t h[4], l[4];
    #pragma unroll
    for (int i = 0; i < 4; i++) h[i] = pack_hi_lo(f[2 * i], f[2 * i + 1], l[i]);
    size_t slab = ((size_t)(c * 2) * Rpad + r) * 32;
    uint32_t sw = (uint32_t)(j ^ ((r >> 1) & 3)) << 4;
    *(uint4*)((char*)(out + slab) + sw) = make_uint4(h[0], h[1], h[2], h[3]);
    *(uint4*)((char*)(out + slab) + (size_t)Rpad * 64 + sw) = make_uint4(l[0], l[1], l[2], l[3]);
}

__global__ void split_gen(const float* __restrict__ w, __nv_bfloat16* __restrict__ out,
                          int Rpad, int K, int nunits)
{
    int u = blockIdx.x * blockDim.x + threadIdx.x;
    if (u < nunits) split_unit(w, out, Rpad, K, u);
}

__global__ void split_weights(const float* xe, const float* se, const float* hh,
                              const float* ih, const float* fc)
{
    int u = blockIdx.x * blockDim.x + threadIdx.x;
    if (u < 32768)  { split_unit(xe, g_xe_t, 512, 512, u); return; }  u -= 32768;
    if (u < 32768)  { split_unit(se, g_se_t, 512, 512, u); return; }  u -= 32768;
    if (u < 98304)  { split_unit(hh, g_hh_t, 1536, 512, u); return; } u -= 98304;
    if (u < 196608) { split_unit(ih, g_ih_t, 1536, 1024, u); return; } u -= 196608;
    if (u < 424000) { split_unit(fc, g_fc_t, 6656, 512, u); }
}

// tiled scalar-pair writer (for cc / h producers)
__device__ __forceinline__ void store_pair_tiled(__nv_bfloat16* base, int Rpad,
                                                 int r, int col, float v0, float v1)
{
    uint32_t lo, hi = pack_hi_lo(v0, v1, lo);
    int c = col >> 5, k = col & 31, j = k >> 3;
    size_t slab = ((size_t)(c * 2) * Rpad + r) * 32;
    uint32_t sw = ((uint32_t)(j ^ ((r >> 1) & 3)) << 4) + (k & 7) * 2;
    *(uint32_t*)((char*)(base + slab) + sw) = hi;
    *(uint32_t*)((char*)(base + slab) + (size_t)Rpad * 64 + sw) = lo;
}

// ---------------- bulk-loaded GEMM (M-tile 64, N-tile 256, 3 stages, 512 thr) ----------------
#define STG_G   40960
#define MB_G    (3 * STG_G)
#define SMEM_G  (MB_G + 64)

__device__ __forceinline__ void issue64(uint32_t stbase, uint32_t mb,
        const __nv_bfloat16* At, int RpadA, int m0,
        const __nv_bfloat16* Wt, int RpadW, int nb, int chunk)
{
    MB_EXPECT(mb, 40960u);
    const char* a0 = (const char*)(At + ((size_t)(chunk * 2 + 0) * RpadA + m0) * 32);
    const char* a1 = (const char*)(At + ((size_t)(chunk * 2 + 1) * RpadA + m0) * 32);
    const char* w0 = (const char*)(Wt + ((size_t)(chunk * 2 + 0) * RpadW + nb) * 32);
    const char* w1 = (const char*)(Wt + ((size_t)(chunk * 2 + 1) * RpadW + nb) * 32);
    BULK_G2S(stbase,          a0, 4096u,  mb);
    BULK_G2S(stbase + 4096,   a1, 4096u,  mb);
    BULK_G2S(stbase + 8192,   w0, 16384u, mb);
    BULK_G2S(stbase + 24576,  w1, 16384u, mb);
}

// warp tile 16x64 (16 warps cover 64x256)
__device__ __forceinline__ void cchunk64(uint32_t aB, uint32_t wB, int lane,
                                         int wm, int wn, float (&acc)[8][4])
{
    #pragma unroll
    for (int ks = 0; ks < 2; ++ks) {
        uint32_t Ah[4], Al[4];
        {
            int row = wm + (lane & 15);
            uint32_t col = (uint32_t)((ks * 2 + (lane >> 4)) ^ ((row >> 1) & 3));
            uint32_t off = (uint32_t)row * 64 + col * 16;
            ldmx4(aB + off, Ah);
            ldmx4(aB + 4096 + off, Al);
        }
        #pragma unroll
        for (int g = 0; g < 4; ++g) {
            int row = wn + g * 16 + ((lane >> 4) << 3) + (lane & 7);
            uint32_t col = (uint32_t)((ks * 2 + ((lane >> 3) & 1)) ^ ((row >> 1) & 3));
            uint32_t off = (uint32_t)row * 64 + col * 16;
            uint32_t bh[4], bl[4];
            ldmx4(wB + off, bh);
            ldmx4(wB + 16384 + off, bl);
            #pragma unroll
            for (int h = 0; h < 2; ++h) {
                float* c = acc[g * 2 + h];
                mma_bf16(c, Ah, bh[2 * h], bh[2 * h + 1]);
                mma_bf16(c, Al, bh[2 * h], bh[2 * h + 1]);
                mma_bf16(c, Ah, bl[2 * h], bl[2 * h + 1]);
            }
        }
    }
}

template<bool GUARD>
__global__ void __launch_bounds__(512, 1)
bulk_gemm(const __nv_bfloat16* __restrict__ At, int RpadA,
          const __nv_bfloat16* __restrict__ Wt, int RpadW,
          const float* __restrict__ bias, float* __restrict__ C, int N, int K)
{
    extern __shared__ char smc[];
    uint32_t sm = smem_u32(smc);
    int tid = threadIdx.x, lane = tid & 31, wid = tid >> 5;
    int wm = (wid >> 2) * 16, wn = (wid & 3) * 64;
    int m0 = blockIdx.y * 64, nb = blockIdx.x * 256;
    uint32_t mb = sm + MB_G;
    int NC = K >> 5;

    if (tid == 0) {
        for (int s = 0; s < 3; s++) MBAR_INIT(mb + 8 * s, 1);
    }
    __syncthreads();
    if (tid == 0) {
        FENCE_ASYNC();
        for (int s = 0; s < 3; s++)
            issue64(sm + s * STG_G, mb + 8 * s, At, RpadA, m0, Wt, RpadW, nb, s);
    }

    float acc[8][4] = {};
    for (int c = 0; c < NC; ++c) {
        int st = c % 3;
        mbar_wait(mb + 8 * st, (uint32_t)((c / 3) & 1));
        cchunk64(sm + st * STG_G, sm + st * STG_G + 8192, lane, wm, wn, acc);
        __syncthreads();
        if (tid == 0 && c + 3 < NC) {
            FENCE_ASYNC();
            issue64(sm + st * STG_G, mb + 8 * st, At, RpadA, m0, Wt, RpadW, nb, c + 3);
        }
    }

    {
        int r1 = m0 + wm + (lane >> 2), r2 = r1 + 8;
        #pragma unroll
        for (int nt = 0; nt < 8; ++nt) {
            int n = nb + wn + nt * 8 + 2 * (lane & 3);
            if (!GUARD || n < N) {
                float b0 = bias[n];
                C[(size_t)r1 * N + n] = acc[nt][0] + b0;
                C[(size_t)r2 * N + n] = acc[nt][2] + b0;
                if (!GUARD || n + 1 < N) {
                    float b1 = bias[n + 1];
                    C[(size_t)r1 * N + n + 1] = acc[nt][1] + b1;
                    C[(size_t)r2 * N + n + 1] = acc[nt][3] + b1;
                }
            }
        }
    }
}

// ---------------- scores kernel (M-tile 128, N-tile 256, 3 stages, 512 thr) ----------------
#define STG_S   49152
#define TAB_S   (3 * STG_S)
#define MB_S    (TAB_S + 4096)
#define SMEM_S  (MB_S + 64)

__device__ __forceinline__ void issue128(uint32_t stbase, uint32_t mb, int m0, int nb, int chunk)
{
    MB_EXPECT(mb, 49152u);
    const char* a0 = (const char*)(g_x_t + ((size_t)(chunk * 2 + 0) * 65536 + m0) * 32);
    const char* a1 = (const char*)(g_x_t + ((size_t)(chunk * 2 + 1) * 65536 + m0) * 32);
    const char* w0 = (const char*)(g_xe_t + ((size_t)(chunk * 2 + 0) * 512 + nb) * 32);
    const char* w1 = (const char*)(g_xe_t + ((size_t)(chunk * 2 + 1) * 512 + nb) * 32);
    BULK_G2S(stbase,          a0, 8192u,  mb);
    BULK_G2S(stbase + 8192,   a1, 8192u,  mb);
    BULK_G2S(stbase + 16384,  w0, 16384u, mb);
    BULK_G2S(stbase + 32768,  w1, 16384u, mb);
}

// warp tile 32x64 (16 warps cover 128x256)
__device__ __forceinline__ void cchunk128(uint32_t aB, uint32_t wB, int lane,
                                          int wm, int wn, float (&acc)[2][8][4])
{
    #pragma unroll
    for (int ks = 0; ks < 2; ++ks) {
        uint32_t Ah[2][4], Al[2][4];
        #pragma unroll
        for (int mt = 0; mt < 2; ++mt) {
            int row = wm + mt * 16 + (lane & 15);
            uint32_t col = (uint32_t)((ks * 2 + (lane >> 4)) ^ ((row >> 1) & 3));
            uint32_t off = (uint32_t)row * 64 + col * 16;
            ldmx4(aB + off, Ah[mt]);
            ldmx4(aB + 8192 + off, Al[mt]);
        }
        #pragma unroll
        for (int g = 0; g < 4; ++g) {
            int row = wn + g * 16 + ((lane >> 4) << 3) + (lane & 7);
            uint32_t col = (uint32_t)((ks * 2 + ((lane >> 3) & 1)) ^ ((row >> 1) & 3));
            uint32_t off = (uint32_t)row * 64 + col * 16;
            uint32_t bh[4], bl[4];
            ldmx4(wB + off, bh);
            ldmx4(wB + 16384 + off, bl);
            #pragma unroll
            for (int mt = 0; mt < 2; ++mt)
                #pragma unroll
                for (int h = 0; h < 2; ++h) {
                    float* c = acc[mt][g * 2 + h];
                    mma_bf16(c, Ah[mt], bh[2 * h], bh[2 * h + 1]);
                    mma_bf16(c, Al[mt], bh[2 * h], bh[2 * h + 1]);
                    mma_bf16(c, Ah[mt], bl[2 * h], bl[2 * h + 1]);
                }
        }
    }
}

__global__ void __launch_bounds__(512, 1)
bulk_scores(const float* __restrict__ xe_b, const float* __restrict__ we)
{
    extern __shared__ char smc[];
    uint32_t sm = smem_u32(smc);
    int tid = threadIdx.x, lane = tid & 31, wid = tid >> 5;
    int wm = (wid >> 2) * 32, wn = (wid & 3) * 64;
    int wx = wid & 3;
    int m0 = blockIdx.y * 128, nb = blockIdx.x * 256;
    int bidx = blockIdx.y >> 1;
    uint32_t mb = sm + MB_S;

    float* cb_s = (float*)(smc + TAB_S);
    float* we_s = cb_s + 256;
    float* part = we_s + 256;
    if (tid < 256) {
        cb_s[tid] = xe_b[nb + tid] + g_sProj[bidx * 512 + nb + tid];
        we_s[tid] = we[nb + tid];
    }

    if (tid == 0) {
        for (int s = 0; s < 3; s++) MBAR_INIT(mb + 8 * s, 1);
    }
    __syncthreads();
    if (tid == 0) {
        FENCE_ASYNC();
        for (int s = 0; s < 3; s++)
            issue128(sm + s * STG_S, mb + 8 * s, m0, nb, s);
    }

    float acc[2][8][4] = {};
    const int NC = 16;
    for (int c = 0; c < NC; ++c) {
        int st = c % 3;
        mbar_wait(mb + 8 * st, (uint32_t)((c / 3) & 1));
        cchunk128(sm + st * STG_S, sm + st * STG_S + 16384, lane, wm, wn, acc);
        __syncthreads();
        if (tid == 0 && c + 3 < NC) {
            FENCE_ASYNC();
            issue128(sm + st * STG_S, mb + 8 * st, m0, nb, c + 3);
        }
    }

    #pragma unroll
    for (int mt = 0; mt < 2; ++mt) {
        float s1 = 0.f, s2 = 0.f;
        #pragma unroll
        for (int nt = 0; nt < 8; ++nt) {
            int n = wn + nt * 8 + 2 * (lane & 3);
            float c0 = cb_s[n], c1 = cb_s[n + 1];
            float w0 = we_s[n], w1 = we_s[n + 1];
            s1 += tanh_fast(acc[mt][nt][0] + c0) * w0 + tanh_fast(acc[mt][nt][1] + c1) * w1;
            s2 += tanh_fast(acc[mt][nt][2] + c0) * w0 + tanh_fast(acc[mt][nt][3] + c1) * w1;
        }
        s1 += __shfl_xor_sync(0xffffffffu, s1, 1); s1 += __shfl_xor_sync(0xffffffffu, s1, 2);
        s2 += __shfl_xor_sync(0xffffffffu, s2, 1); s2 += __shfl_xor_sync(0xffffffffu, s2, 2);
        if ((lane & 3) == 0) {
            int rl = wm + mt * 16 + (lane >> 2);
            part[wx * 128 + rl]     = s1;
            part[wx * 128 + rl + 8] = s2;
        }
    }
    __syncthreads();
    if (tid < 128)
        g_spart[blockIdx.x * 65536 + m0 + tid] =
            part[tid] + part[128 + tid] + part[256 + tid] + part[384 + tid];
}

// ---------------- fused softmax + context + cc (tiled output) ----------------
__global__ void softmax_ctx_cc(const float* __restrict__ x,
                               const float* __restrict__ emb,
                               const int* __restrict__ yPrev)
{
    int b = blockIdx.x, t = threadIdx.x;
    __shared__ float al[T_];
    __shared__ float red[T_];
    float v = g_spart[b * 256 + t] + g_spart[65536 + b * 256 + t];
    red[t] = v; __syncthreads();
    for (int s = 128; s; s >>= 1) { if (t < s) red[t] = fmaxf(red[t], red[t + s]); __syncthreads(); }
    float mx = red[0]; __syncthreads();
    float e = expf(v - mx);
    red[t] = e; __syncthreads();
    for (int s = 128; s; s >>= 1) { if (t < s) red[t] += red[t + s]; __syncthreads(); }
    al[t] = e / red[0];
    __syncthreads();

    const float* xb = x + (size_t)b * 256 * 512;
    float c0 = 0.f, c1 = 0.f;
    #pragma unroll 4
    for (int tt = 0; tt < 256; ++tt) {
        float a = al[tt];
        float2 xv = *(const float2*)(xb + (size_t)tt * 512 + 2 * t);
        c0 += a * xv.x; c1 += a * xv.y;
    }
    store_pair_tiled(g_cc_t, 256, b, 512 + 2 * t, c0, c1);

    int y = yPrev[b];
    float2 ev = *(const float2*)(emb + (size_t)y * 512 + 2 * t);
    store_pair_tiled(g_cc_t, 256, b, 2 * t, ev.x, ev.y);
}

// ---------------- GRU elementwise (tiled h output) ----------------
__global__ void gru_kernel(const float* __restrict__ s, float* __restrict__ h_out)
{
    int b = blockIdx.x, t = threadIdx.x;
    float hv[2];
    #pragma unroll
    for (int q = 0; q < 2; ++q) {
        int j = 2 * t + q;
        float ir = g_gi[b * 1536 + j];
        float iz = g_gi[b * 1536 + 512 + j];
        float in_ = g_gi[b * 1536 + 1024 + j];
        float hr = g_gh[b * 1536 + j];
        float hz = g_gh[b * 1536 + 512 + j];
        float hn = g_gh[b * 1536 + 1024 + j];
        float r = 1.f / (1.f + expf(-(ir + hr)));
        float z = 1.f / (1.f + expf(-(iz + hz)));
        float n = tanhf(in_ + r * hn);
        hv[q] = (1.f - z) * n + z * s[b * 512 + j];
        if (h_out) h_out[b * 512 + j] = hv[q];
    }
    store_pair_tiled(g_h_t, 256, b, 2 * t, hv[0], hv[1]);
}

// ======================================================================
extern "C" void kernel_launch(void* const* d_in, const int* in_sizes, int n_in,
                              void* d_out, int out_size)
{
    const float* x     = (const float*)d_in[0];
    const float* sPrev = (const float*)d_in[1];
    const int*   yPrev = (const int*)  d_in[2];
    const float* xe_w  = (const float*)d_in[3];
    const float* xe_b  = (const float*)d_in[4];
    const float* se_w  = (const float*)d_in[5];
    const float* se_b  = (const float*)d_in[6];
    const float* we_w  = (const float*)d_in[7];
    const float* emb   = (const float*)d_in[9];
    const float* w_ih  = (const float*)d_in[10];
    const float* w_hh  = (const float*)d_in[11];
    const float* b_ih  = (const float*)d_in[12];
    const float* b_hh  = (const float*)d_in[13];
    const float* fc_w  = (const float*)d_in[14];
    const float* fc_b  = (const float*)d_in[15];

    float* out = (float*)d_out;
    float* h_out = (out_size >= B_ * YD_ + B_ * 512) ? out + (size_t)B_ * YD_ : nullptr;

    float *sProj_p, *gi_p, *gh_p;
    cudaGetSymbolAddress((void**)&sProj_p, g_sProj);
    cudaGetSymbolAddress((void**)&gi_p, g_gi);
    cudaGetSymbolAddress((void**)&gh_p, g_gh);
    __nv_bfloat16 *x_t, *s_t, *cc_t, *h_t, *se_t, *hh_t, *ih_t, *fc_t;
    cudaGetSymbolAddress((void**)&x_t,  g_x_t);
    cudaGetSymbolAddress((void**)&s_t,  g_s_t);
    cudaGetSymbolAddress((void**)&cc_t, g_cc_t);
    cudaGetSymbolAddress((void**)&h_t,  g_h_t);
    cudaGetSymbolAddress((void**)&se_t, g_se_t);
    cudaGetSymbolAddress((void**)&hh_t, g_hh_t);
    cudaGetSymbolAddress((void**)&ih_t, g_ih_t);
    cudaGetSymbolAddress((void**)&fc_t, g_fc_t);

    static cudaStream_t s2 = nullptr;
    static cudaEvent_t evFork = nullptr, evW = nullptr, evX = nullptr, evGH = nullptr;
    if (!s2) {
        cudaFuncSetAttribute(bulk_scores,      cudaFuncAttributeMaxDynamicSharedMemorySize, SMEM_S);
        cudaFuncSetAttribute(bulk_gemm<false>, cudaFuncAttributeMaxDynamicSharedMemorySize, SMEM_G);
        cudaFuncSetAttribute(bulk_gemm<true>,  cudaFuncAttributeMaxDynamicSharedMemorySize, SMEM_G);
        cudaStreamCreateWithFlags(&s2, cudaStreamNonBlocking);
        cudaEventCreateWithFlags(&evFork, cudaEventDisableTiming);
        cudaEventCreateWithFlags(&evW, cudaEventDisableTiming);
        cudaEventCreateWithFlags(&evX, cudaEventDisableTiming);
        cudaEventCreateWithFlags(&evGH, cudaEventDisableTiming);
    }

    // ---- capture fork ----
    cudaEventRecord(evFork, 0);
    cudaStreamWaitEvent(s2, evFork, 0);

    // ---- stream 2: x split (independent of weights) ----
    split_gen<<<16384, 256, 0, s2>>>(x, x_t, 65536, 512, 65536 * 64);
    cudaEventRecord(evX, s2);

    // ---- stream 1 (capture stream): s split, weight splits ----
    split_gen<<<64, 256>>>(sPrev, s_t, 256, 512, 256 * 64);
    split_weights<<<(784448 + 255) / 256, 256>>>(xe_w, se_w, w_hh, w_ih, fc_w);
    cudaEventRecord(evW, 0);

    // gh on s2 (needs weights + s split)
    cudaStreamWaitEvent(s2, evW, 0);
    bulk_gemm<false><<<dim3(6, 4), 512, SMEM_G, s2>>>(s_t, 256, hh_t, 1536, b_hh, gh_p, 1536, 512);
    cudaEventRecord(evGH, s2);

    // ---- main chain ----
    bulk_gemm<false><<<dim3(2, 4), 512, SMEM_G>>>(s_t, 256, se_t, 512, se_b, sProj_p, 512, 512);
    cudaStreamWaitEvent(0, evX, 0);
    bulk_scores<<<dim3(2, 512), 512, SMEM_S>>>(xe_b, we_w);
    softmax_ctx_cc<<<256, 256>>>(x, emb, yPrev);
    bulk_gemm<false><<<dim3(6, 4), 512, SMEM_G>>>(cc_t, 256, ih_t, 1536, b_ih, gi_p, 1536, 1024);
    cudaStreamWaitEvent(0, evGH, 0);
    gru_kernel<<<256, 256>>>(sPrev, h_out);
    bulk_gemm<true><<<dim3(26, 4), 512, SMEM_G>>>(h_t, 256, fc_t, 6656, fc_b, out, 6625, 512);
}

// round 10
// speedup vs baseline: 1.0883x; 1.0883x over previous
#include <cuda_runtime.h>
#include <cuda_bf16.h>
#include <math.h>
#include <stdint.h>

#define B_  256
#define T_  256
#define YD_ 6625

// ---------------- fp32 scratch ----------------
__device__ float g_sProj[256 * 512];      // = s@se_w^T + (se_b + xe_b)
__device__ float g_spart[2 * 65536];
__device__ float g_gi[256 * 1536];
__device__ float g_gh[256 * 1536];
__device__ float g_cbias[512];            // se_b + xe_b

// ---------------- chunk-tiled, pre-swizzled bf16 scratch ----------------
// slab(c, plane) = base + (c*2+plane)*Rpad*32 elems; row r at +r*32 elems (64B);
// within row, 16B unit j stored at (j ^ ((r>>1)&3)).
__device__ __nv_bfloat16 g_x_t [16u * 2 * 65536 * 32];
__device__ __nv_bfloat16 g_s_t [16 * 2 * 256 * 32];
__device__ __nv_bfloat16 g_cc_t[32 * 2 * 256 * 32];
__device__ __nv_bfloat16 g_h_t [16 * 2 * 256 * 32];
__device__ __nv_bfloat16 g_xe_t[16 * 2 * 512 * 32];
__device__ __nv_bfloat16 g_se_t[16 * 2 * 512 * 32];
__device__ __nv_bfloat16 g_hh_t[16 * 2 * 1536 * 32];
__device__ __nv_bfloat16 g_ih_t[32 * 2 * 1536 * 32];
__device__ __nv_bfloat16 g_fc_t[16 * 2 * 6656 * 32];

// ---------------- helpers ----------------
__device__ __forceinline__ uint32_t smem_u32(const void* p) {
    uint32_t a;
    asm("{ .reg .u64 t; cvta.to.shared.u64 t, %1; cvt.u32.u64 %0, t; }" : "=r"(a) : "l"(p));
    return a;
}
__device__ __forceinline__ void ldmx4(uint32_t addr, uint32_t* r) {
    asm volatile("ldmatrix.sync.aligned.m8n8.x4.shared.b16 {%0,%1,%2,%3}, [%4];"
        : "=r"(r[0]), "=r"(r[1]), "=r"(r[2]), "=r"(r[3]) : "r"(addr));
}
__device__ __forceinline__ void mma_bf16(float* c, const uint32_t* a, uint32_t b0, uint32_t b1) {
    asm volatile("mma.sync.aligned.m16n8k16.row.col.f32.bf16.bf16.f32 "
        "{%0,%1,%2,%3}, {%4,%5,%6,%7}, {%8,%9}, {%0,%1,%2,%3};"
        : "+f"(c[0]), "+f"(c[1]), "+f"(c[2]), "+f"(c[3])
        : "r"(a[0]), "r"(a[1]), "r"(a[2]), "r"(a[3]), "r"(b0), "r"(b1));
}
#define MBAR_INIT(mb, c) asm volatile("mbarrier.init.shared.b64 [%0], %1;" :: "r"(mb), "r"(c) : "memory")
#define MB_EXPECT(mb, n) asm volatile("mbarrier.arrive.expect_tx.shared.b64 _, [%0], %1;" :: "r"(mb), "r"(n) : "memory")
#define FENCE_ASYNC()    asm volatile("fence.proxy.async.shared::cta;" ::: "memory")
#define BULK_G2S(dst, src, sz, mb) \
    asm volatile("cp.async.bulk.shared::cluster.global.mbarrier::complete_tx::bytes [%0], [%1], %2, [%3];" \
        :: "r"(dst), "l"(src), "r"(sz), "r"(mb) : "memory")

__device__ __forceinline__ void mbar_wait(uint32_t mb, uint32_t phase) {
    asm volatile(
        "{\n\t.reg .pred P;\n\t"
        "WL%=:\n\t"
        "mbarrier.try_wait.parity.acquire.cta.shared::cta.b64 P, [%0], %1, 0x989680;\n\t"
        "@!P bra WL%=;\n\t}"
        :: "r"(mb), "r"(phase) : "memory");
}

__device__ __forceinline__ float tanh_fast(float x) {
    float xc = fminf(fmaxf(x, -15.f), 15.f);
    float e = exp2f(xc * 2.8853900817779268f);
    return __fdividef(e - 1.0f, e + 1.0f);
}
__device__ __forceinline__ uint32_t pack_hi_lo(float a, float b, uint32_t& lo) {
    __nv_bfloat16 ha = __float2bfloat16(a), hb = __float2bfloat16(b);
    __nv_bfloat16 la = __float2bfloat16(a - __bfloat162float(ha));
    __nv_bfloat16 lb = __float2bfloat16(b - __bfloat162float(hb));
    lo = (uint32_t)*(unsigned short*)&la | ((uint32_t)*(unsigned short*)&lb << 16);
    return (uint32_t)*(unsigned short*)&ha | ((uint32_t)*(unsigned short*)&hb << 16);
}

// ---------------- split writers ----------------
__device__ __forceinline__ void split_unit(const float* __restrict__ w,
                                           __nv_bfloat16* __restrict__ out,
                                           int Rpad, int K, int u)
{
    int upr = K >> 3;
    int r = u / upr, uu = u - r * upr;
    int c = uu >> 2, j = uu & 3;
    const float4* src = (const float4*)(w + (size_t)r * K + c * 32 + j * 8);
    float4 v0 = src[0], v1 = src[1];
    float f[8] = {v0.x, v0.y, v0.z, v0.w, v1.x, v1.y, v1.z, v1.w};
    uint32_t h[4], l[4];
    #pragma unroll
    for (int i = 0; i < 4; i++) h[i] = pack_hi_lo(f[2 * i], f[2 * i + 1], l[i]);
    size_t slab = ((size_t)(c * 2) * Rpad + r) * 32;
    uint32_t sw = (uint32_t)(j ^ ((r >> 1) & 3)) << 4;
    *(uint4*)((char*)(out + slab) + sw) = make_uint4(h[0], h[1], h[2], h[3]);
    *(uint4*)((char*)(out + slab) + (size_t)Rpad * 64 + sw) = make_uint4(l[0], l[1], l[2], l[3]);
}

__global__ void split_gen(const float* __restrict__ w, __nv_bfloat16* __restrict__ out,
                          int Rpad, int K, int nunits)
{
    int u = blockIdx.x * blockDim.x + threadIdx.x;
    if (u < nunits) split_unit(w, out, Rpad, K, u);
}

#define Q_TOT 784448
__global__ void split_weights(const float* xe, const float* se, const float* hh,
                              const float* ih, const float* fc,
                              const float* se_b, const float* xe_b)
{
    int u = blockIdx.x * blockDim.x + threadIdx.x;
    if (u < 32768)  { split_unit(xe, g_xe_t, 512, 512, u); return; }  u -= 32768;
    if (u < 32768)  { split_unit(se, g_se_t, 512, 512, u); return; }  u -= 32768;
    if (u < 98304)  { split_unit(hh, g_hh_t, 1536, 512, u); return; } u -= 98304;
    if (u < 196608) { split_unit(ih, g_ih_t, 1536, 1024, u); return; } u -= 196608;
    if (u < 424000) { split_unit(fc, g_fc_t, 6656, 512, u); return; } u -= 424000;
    if (u < 512)    { g_cbias[u] = se_b[u] + xe_b[u]; }
}

// tiled scalar-pair writer
__device__ __forceinline__ void store_pair_tiled(__nv_bfloat16* base, int Rpad,
                                                 int r, int col, float v0, float v1)
{
    uint32_t lo, hi = pack_hi_lo(v0, v1, lo);
    int c = col >> 5, k = col & 31, j = k >> 3;
    size_t slab = ((size_t)(c * 2) * Rpad + r) * 32;
    uint32_t sw = ((uint32_t)(j ^ ((r >> 1) & 3)) << 4) + (k & 7) * 2;
    *(uint32_t*)((char*)(base + slab) + sw) = hi;
    *(uint32_t*)((char*)(base + slab) + (size_t)Rpad * 64 + sw) = lo;
}

// ============ small GEMM: M-tile 64, N-tile 128, 3 stages, 256 thr ============
#define STG_G   24576            // Ahi 4K | Alo 4K | Whi 8K | Wlo 8K
#define MB_G    (3 * STG_G)      // 73728
#define SMEM_G  (MB_G + 64)

__device__ __forceinline__ void issue64(uint32_t stbase, uint32_t mb,
        const __nv_bfloat16* At, int RpadA, int m0,
        const __nv_bfloat16* Wt, int RpadW, int nb, int chunk)
{
    MB_EXPECT(mb, 24576u);
    const char* a0 = (const char*)(At + ((size_t)(chunk * 2 + 0) * RpadA + m0) * 32);
    const char* a1 = (const char*)(At + ((size_t)(chunk * 2 + 1) * RpadA + m0) * 32);
    const char* w0 = (const char*)(Wt + ((size_t)(chunk * 2 + 0) * RpadW + nb) * 32);
    const char* w1 = (const char*)(Wt + ((size_t)(chunk * 2 + 1) * RpadW + nb) * 32);
    BULK_G2S(stbase,          a0, 4096u, mb);
    BULK_G2S(stbase + 4096,   a1, 4096u, mb);
    BULK_G2S(stbase + 8192,   w0, 8192u, mb);
    BULK_G2S(stbase + 16384,  w1, 8192u, mb);
}

// warp tile 32x32 (8 warps cover 64x128)
__device__ __forceinline__ void cchunk64(uint32_t aB, uint32_t wB, int lane,
                                         int wm, int wn, float (&acc)[2][4][4])
{
    #pragma unroll
    for (int ks = 0; ks < 2; ++ks) {
        uint32_t Ah[2][4], Al[2][4];
        #pragma unroll
        for (int mt = 0; mt < 2; ++mt) {
            int row = wm + mt * 16 + (lane & 15);
            uint32_t col = (uint32_t)((ks * 2 + (lane >> 4)) ^ ((row >> 1) & 3));
            uint32_t off = (uint32_t)row * 64 + col * 16;
            ldmx4(aB + off, Ah[mt]);
            ldmx4(aB + 4096 + off, Al[mt]);
        }
        #pragma unroll
        for (int g = 0; g < 2; ++g) {
            int row = wn + g * 16 + ((lane >> 4) << 3) + (lane & 7);
            uint32_t col = (uint32_t)((ks * 2 + ((lane >> 3) & 1)) ^ ((row >> 1) & 3));
            uint32_t off = (uint32_t)row * 64 + col * 16;
            uint32_t bh[4], bl[4];
            ldmx4(wB + off, bh);
            ldmx4(wB + 8192 + off, bl);
            #pragma unroll
            for (int mt = 0; mt < 2; ++mt)
                #pragma unroll
                for (int h = 0; h < 2; ++h) {
                    float* c = acc[mt][g * 2 + h];
                    mma_bf16(c, Ah[mt], bh[2 * h], bh[2 * h + 1]);
                    mma_bf16(c, Al[mt], bh[2 * h], bh[2 * h + 1]);
                    mma_bf16(c, Ah[mt], bl[2 * h], bl[2 * h + 1]);
                }
        }
    }
}

template<bool GUARD>
__global__ void __launch_bounds__(256, 1)
bulk_gemm(const __nv_bfloat16* __restrict__ At, int RpadA,
          const __nv_bfloat16* __restrict__ Wt, int RpadW,
          const float* __restrict__ bias, float* __restrict__ C, int N, int K)
{
    extern __shared__ char smc[];
    uint32_t sm = smem_u32(smc);
    int tid = threadIdx.x, lane = tid & 31, wid = tid >> 5;
    int wm = (wid >> 2) * 32, wn = (wid & 3) * 32;
    int m0 = blockIdx.y * 64, nb = blockIdx.x * 128;
    uint32_t mb = sm + MB_G;
    int NC = K >> 5;

    if (tid == 0) {
        for (int s = 0; s < 3; s++) MBAR_INIT(mb + 8 * s, 1);
    }
    __syncthreads();
    if (tid == 0) {
        FENCE_ASYNC();
        for (int s = 0; s < 3; s++)
            issue64(sm + s * STG_G, mb + 8 * s, At, RpadA, m0, Wt, RpadW, nb, s);
    }

    float acc[2][4][4] = {};
    for (int c = 0; c < NC; ++c) {
        int st = c % 3;
        mbar_wait(mb + 8 * st, (uint32_t)((c / 3) & 1));
        cchunk64(sm + st * STG_G, sm + st * STG_G + 8192, lane, wm, wn, acc);
        __syncthreads();
        if (tid == 0 && c + 3 < NC) {
            FENCE_ASYNC();
            issue64(sm + st * STG_G, mb + 8 * st, At, RpadA, m0, Wt, RpadW, nb, c + 3);
        }
    }

    #pragma unroll
    for (int mt = 0; mt < 2; ++mt) {
        int r1 = m0 + wm + mt * 16 + (lane >> 2), r2 = r1 + 8;
        #pragma unroll
        for (int nt = 0; nt < 4; ++nt) {
            int n = nb + wn + nt * 8 + 2 * (lane & 3);
            if (!GUARD || n < N) {
                float b0 = bias[n];
                C[(size_t)r1 * N + n] = acc[mt][nt][0] + b0;
                C[(size_t)r2 * N + n] = acc[mt][nt][2] + b0;
                if (!GUARD || n + 1 < N) {
                    float b1 = bias[n + 1];
                    C[(size_t)r1 * N + n + 1] = acc[mt][nt][1] + b1;
                    C[(size_t)r2 * N + n + 1] = acc[mt][nt][3] + b1;
                }
            }
        }
    }
}

// ============ persistent scores kernel: grid 148, 256 thr, tile 128x256 ============
#define STG_S   49152            // Ahi 8K | Alo 8K | Whi 16K | Wlo 16K
#define TAB_S   (3 * STG_S)      // 147456: we 2K | cbbuf 2K | part 2K
#define MB_S    (TAB_S + 6144)   // 153600
#define SMEM_S  (MB_S + 64)
#define NTILES  1024
#define GRID_S  148

__device__ __forceinline__ void issue128(uint32_t stbase, uint32_t mb, int m0, int nb, int chunk)
{
    MB_EXPECT(mb, 49152u);
    const char* a0 = (const char*)(g_x_t + ((size_t)(chunk * 2 + 0) * 65536 + m0) * 32);
    const char* a1 = (const char*)(g_x_t + ((size_t)(chunk * 2 + 1) * 65536 + m0) * 32);
    const char* w0 = (const char*)(g_xe_t + ((size_t)(chunk * 2 + 0) * 512 + nb) * 32);
    const char* w1 = (const char*)(g_xe_t + ((size_t)(chunk * 2 + 1) * 512 + nb) * 32);
    BULK_G2S(stbase,          a0, 8192u,  mb);
    BULK_G2S(stbase + 8192,   a1, 8192u,  mb);
    BULK_G2S(stbase + 16384,  w0, 16384u, mb);
    BULK_G2S(stbase + 32768,  w1, 16384u, mb);
}

// warp tile 64x64 (8 warps cover 128x256)
__device__ __forceinline__ void cchunk128(uint32_t aB, uint32_t wB, int lane,
                                          int wm, int wn, float (&acc)[4][8][4])
{
    #pragma unroll
    for (int ks = 0; ks < 2; ++ks) {
        uint32_t Ah[4][4], Al[4][4];
        #pragma unroll
        for (int mt = 0; mt < 4; ++mt) {
            int row = wm + mt * 16 + (lane & 15);
            uint32_t col = (uint32_t)((ks * 2 + (lane >> 4)) ^ ((row >> 1) & 3));
            uint32_t off = (uint32_t)row * 64 + col * 16;
            ldmx4(aB + off, Ah[mt]);
            ldmx4(aB + 8192 + off, Al[mt]);
        }
        #pragma unroll
        for (int g = 0; g < 4; ++g) {
            int row = wn + g * 16 + ((lane >> 4) << 3) + (lane & 7);
            uint32_t col = (uint32_t)((ks * 2 + ((lane >> 3) & 1)) ^ ((row >> 1) & 3));
            uint32_t off = (uint32_t)row * 64 + col * 16;
            uint32_t bh[4], bl[4];
            ldmx4(wB + off, bh);
            ldmx4(wB + 16384 + off, bl);
            #pragma unroll
            for (int mt = 0; mt < 4; ++mt)
                #pragma unroll
                for (int h = 0; h < 2; ++h) {
                    float* c = acc[mt][g * 2 + h];
                    mma_bf16(c, Ah[mt], bh[2 * h], bh[2 * h + 1]);
                    mma_bf16(c, Al[mt], bh[2 * h], bh[2 * h + 1]);
                    mma_bf16(c, Ah[mt], bl[2 * h], bl[2 * h + 1]);
                }
        }
    }
}

__device__ __forceinline__ void issue_tile(uint32_t sm, uint32_t mb, int bid, int gq)
{
    int t = bid + (gq >> 4) * GRID_S;
    int chunk = gq & 15;
    int m0 = (t >> 1) << 7;
    int nb = (t & 1) << 8;
    int st = gq % 3;
    issue128(sm + st * STG_S, mb + 8 * st, m0, nb, chunk);
}

__global__ void __launch_bounds__(256, 1)
bulk_scores(const float* __restrict__ we)
{
    extern __shared__ char smc[];
    uint32_t sm = smem_u32(smc);
    int tid = threadIdx.x, lane = tid & 31, wid = tid >> 5;
    int wm = (wid >> 2) * 64, wn = (wid & 3) * 64;
    int wx = wid & 3;
    int bid = blockIdx.x;
    uint32_t mb = sm + MB_S;

    float* we_s  = (float*)(smc + TAB_S);        // 512
    float* cbbuf = we_s + 512;                   // 2 x 256
    float* part  = cbbuf + 512;                  // 512

    we_s[tid]       = we[tid];
    we_s[tid + 256] = we[tid + 256];

    int nt_cta = (NTILES - bid + GRID_S - 1) / GRID_S;
    int total = nt_cta * 16;

    if (tid == 0) {
        for (int s = 0; s < 3; s++) MBAR_INIT(mb + 8 * s, 1);
    }
    __syncthreads();
    if (tid == 0) {
        FENCE_ASYNC();
        for (int s = 0; s < 3; s++) issue_tile(sm, mb, bid, s);
    }

    float acc[4][8][4] = {};
    for (int gq = 0; gq < total; ++gq) {
        int tt = gq >> 4;
        int t  = bid + tt * GRID_S;
        if ((gq & 15) == 0) {
            // prefetch this tile's cb into the parity buffer (no race: the
            // buffer's previous reader finished >=16 chunks / syncs ago)
            int bidx = t >> 2;
            int nb   = (t & 1) << 8;
            cbbuf[(tt & 1) * 256 + tid] = g_sProj[bidx * 512 + nb + tid];
        }
        int st = gq % 3;
        mbar_wait(mb + 8 * st, (uint32_t)((gq / 3) & 1));
        cchunk128(sm + st * STG_S, sm + st * STG_S + 16384, lane, wm, wn, acc);
        __syncthreads();
        if (tid == 0 && gq + 3 < total) {
            FENCE_ASYNC();
            issue_tile(sm, mb, bid, gq + 3);
        }
        if ((gq & 15) == 15) {
            // epilogue for tile t
            int m0 = (t >> 1) << 7;
            int nb = (t & 1) << 8;
            float* cb = cbbuf + (tt & 1) * 256;
            #pragma unroll
            for (int mt = 0; mt < 4; ++mt) {
                float s1 = 0.f, s2 = 0.f;
                #pragma unroll
                for (int ntc = 0; ntc < 8; ++ntc) {
                    int n = wn + ntc * 8 + 2 * (lane & 3);
                    float c0 = cb[n], c1 = cb[n + 1];
                    float w0 = we_s[nb + n], w1 = we_s[nb + n + 1];
                    s1 += tanh_fast(acc[mt][ntc][0] + c0) * w0 + tanh_fast(acc[mt][ntc][1] + c1) * w1;
                    s2 += tanh_fast(acc[mt][ntc][2] + c0) * w0 + tanh_fast(acc[mt][ntc][3] + c1) * w1;
                    acc[mt][ntc][0] = 0.f; acc[mt][ntc][1] = 0.f;
                    acc[mt][ntc][2] = 0.f; acc[mt][ntc][3] = 0.f;
                }
                s1 += __shfl_xor_sync(0xffffffffu, s1, 1); s1 += __shfl_xor_sync(0xffffffffu, s1, 2);
                s2 += __shfl_xor_sync(0xffffffffu, s2, 1); s2 += __shfl_xor_sync(0xffffffffu, s2, 2);
                if ((lane & 3) == 0) {
                    int rl = wm + mt * 16 + (lane >> 2);
                    part[wx * 128 + rl]     = s1;
                    part[wx * 128 + rl + 8] = s2;
                }
            }
            __syncthreads();
            if (tid < 128)
                g_spart[(t & 1) * 65536 + m0 + tid] =
                    part[tid] + part[128 + tid] + part[256 + tid] + part[384 + tid];
        }
    }
}

// ---------------- fused softmax + context + cc ----------------
__global__ void softmax_ctx_cc(const float* __restrict__ x,
                               const float* __restrict__ emb,
                               const int* __restrict__ yPrev)
{
    int b = blockIdx.x, t = threadIdx.x;
    __shared__ float al[T_];
    __shared__ float red[T_];
    float v = g_spart[b * 256 + t] + g_spart[65536 + b * 256 + t];
    red[t] = v; __syncthreads();
    for (int s = 128; s; s >>= 1) { if (t < s) red[t] = fmaxf(red[t], red[t + s]); __syncthreads(); }
    float mx = red[0]; __syncthreads();
    float e = expf(v - mx);
    red[t] = e; __syncthreads();
    for (int s = 128; s; s >>= 1) { if (t < s) red[t] += red[t + s]; __syncthreads(); }
    al[t] = e / red[0];
    __syncthreads();

    const float* xb = x + (size_t)b * 256 * 512;
    float c0 = 0.f, c1 = 0.f;
    #pragma unroll 4
    for (int tt = 0; tt < 256; ++tt) {
        float a = al[tt];
        float2 xv = *(const float2*)(xb + (size_t)tt * 512 + 2 * t);
        c0 += a * xv.x; c1 += a * xv.y;
    }
    store_pair_tiled(g_cc_t, 256, b, 512 + 2 * t, c0, c1);

    int y = yPrev[b];
    float2 ev = *(const float2*)(emb + (size_t)y * 512 + 2 * t);
    store_pair_tiled(g_cc_t, 256, b, 2 * t, ev.x, ev.y);
}

// ---------------- GRU elementwise ----------------
__global__ void gru_kernel(const float* __restrict__ s, float* __restrict__ h_out)
{
    int b = blockIdx.x, t = threadIdx.x;
    float hv[2];
    #pragma unroll
    for (int q = 0; q < 2; ++q) {
        int j = 2 * t + q;
        float ir = g_gi[b * 1536 + j];
        float iz = g_gi[b * 1536 + 512 + j];
        float in_ = g_gi[b * 1536 + 1024 + j];
        float hr = g_gh[b * 1536 + j];
        float hz = g_gh[b * 1536 + 512 + j];
        float hn = g_gh[b * 1536 + 1024 + j];
        float r = 1.f / (1.f + expf(-(ir + hr)));
        float z = 1.f / (1.f + expf(-(iz + hz)));
        float n = tanhf(in_ + r * hn);
        hv[q] = (1.f - z) * n + z * s[b * 512 + j];
        if (h_out) h_out[b * 512 + j] = hv[q];
    }
    store_pair_tiled(g_h_t, 256, b, 2 * t, hv[0], hv[1]);
}

// ======================================================================
extern "C" void kernel_launch(void* const* d_in, const int* in_sizes, int n_in,
                              void* d_out, int out_size)
{
    const float* x     = (const float*)d_in[0];
    const float* sPrev = (const float*)d_in[1];
    const int*   yPrev = (const int*)  d_in[2];
    const float* xe_w  = (const float*)d_in[3];
    const float* xe_b  = (const float*)d_in[4];
    const float* se_w  = (const float*)d_in[5];
    const float* se_b  = (const float*)d_in[6];
    const float* we_w  = (const float*)d_in[7];
    const float* emb   = (const float*)d_in[9];
    const float* w_ih  = (const float*)d_in[10];
    const float* w_hh  = (const float*)d_in[11];
    const float* b_ih  = (const float*)d_in[12];
    const float* b_hh  = (const float*)d_in[13];
    const float* fc_w  = (const float*)d_in[14];
    const float* fc_b  = (const float*)d_in[15];

    float* out = (float*)d_out;
    float* h_out = (out_size >= B_ * YD_ + B_ * 512) ? out + (size_t)B_ * YD_ : nullptr;

    float *sProj_p, *gi_p, *gh_p, *cbias_p;
    cudaGetSymbolAddress((void**)&sProj_p, g_sProj);
    cudaGetSymbolAddress((void**)&gi_p, g_gi);
    cudaGetSymbolAddress((void**)&gh_p, g_gh);
    cudaGetSymbolAddress((void**)&cbias_p, g_cbias);
    __nv_bfloat16 *x_t, *s_t, *cc_t, *h_t, *se_t, *hh_t, *ih_t, *fc_t;
    cudaGetSymbolAddress((void**)&x_t,  g_x_t);
    cudaGetSymbolAddress((void**)&s_t,  g_s_t);
    cudaGetSymbolAddress((void**)&cc_t, g_cc_t);
    cudaGetSymbolAddress((void**)&h_t,  g_h_t);
    cudaGetSymbolAddress((void**)&se_t, g_se_t);
    cudaGetSymbolAddress((void**)&hh_t, g_hh_t);
    cudaGetSymbolAddress((void**)&ih_t, g_ih_t);
    cudaGetSymbolAddress((void**)&fc_t, g_fc_t);

    static cudaStream_t s2 = nullptr;
    static cudaEvent_t evFork = nullptr, evW = nullptr, evX = nullptr, evGH = nullptr;
    if (!s2) {
        cudaFuncSetAttribute(bulk_scores,      cudaFuncAttributeMaxDynamicSharedMemorySize, SMEM_S);
        cudaFuncSetAttribute(bulk_gemm<false>, cudaFuncAttributeMaxDynamicSharedMemorySize, SMEM_G);
        cudaFuncSetAttribute(bulk_gemm<true>,  cudaFuncAttributeMaxDynamicSharedMemorySize, SMEM_G);
        cudaStreamCreateWithFlags(&s2, cudaStreamNonBlocking);
        cudaEventCreateWithFlags(&evFork, cudaEventDisableTiming);
        cudaEventCreateWithFlags(&evW, cudaEventDisableTiming);
        cudaEventCreateWithFlags(&evX, cudaEventDisableTiming);
        cudaEventCreateWithFlags(&evGH, cudaEventDisableTiming);
    }

    // ---- capture fork ----
    cudaEventRecord(evFork, 0);
    cudaStreamWaitEvent(s2, evFork, 0);

    // ---- stream 2: x split ----
    split_gen<<<16384, 256, 0, s2>>>(x, x_t, 65536, 512, 65536 * 64);
    cudaEventRecord(evX, s2);

    // ---- capture stream: s split, weight splits (+ cbias tail) ----
    split_gen<<<64, 256>>>(sPrev, s_t, 256, 512, 256 * 64);
    split_weights<<<(Q_TOT + 512 + 255) / 256, 256>>>(xe_w, se_w, w_hh, w_ih, fc_w, se_b, xe_b);
    cudaEventRecord(evW, 0);

    // gh on s2
    cudaStreamWaitEvent(s2, evW, 0);
    bulk_gemm<false><<<dim3(12, 4), 256, SMEM_G, s2>>>(s_t, 256, hh_t, 1536, b_hh, gh_p, 1536, 512);
    cudaEventRecord(evGH, s2);

    // ---- main chain ----
    bulk_gemm<false><<<dim3(4, 4), 256, SMEM_G>>>(s_t, 256, se_t, 512, cbias_p, sProj_p, 512, 512);
    cudaStreamWaitEvent(0, evX, 0);
    bulk_scores<<<GRID_S, 256, SMEM_S>>>(we_w);
    softmax_ctx_cc<<<256, 256>>>(x, emb, yPrev);
    bulk_gemm<false><<<dim3(12, 4), 256, SMEM_G>>>(cc_t, 256, ih_t, 1536, b_ih, gi_p, 1536, 1024);
    cudaStreamWaitEvent(0, evGH, 0);
    gru_kernel<<<256, 256>>>(sPrev, h_out);
    bulk_gemm<true><<<dim3(52, 4), 256, SMEM_G>>>(h_t, 256, fc_t, 6656, fc_b, out, 6625, 512);
}

// round 11
// speedup vs baseline: 1.3490x; 1.2395x over previous
#include <cuda_runtime.h>
#include <cuda_fp16.h>
#include <math.h>
#include <stdint.h>

#define B_  256
#define T_  256
#define YD_ 6625

// ---------------- fp32 scratch ----------------
__device__ float g_sProj[256 * 512];      // = s@se_w^T + (se_b + xe_b)
__device__ float g_spart[2 * 65536];
__device__ float g_gi[256 * 1536];
__device__ float g_gh[256 * 1536];
__device__ float g_cbias[512];

// ---------------- chunk-tiled, pre-swizzled fp16 scratch ----------------
// slab(c, plane) = base + (c*2+plane)*Rpad*32 elems; row r at +r*32 elems (64B);
// within row, 16B unit j stored at (j ^ ((r>>1)&3)).
__device__ __half g_x_t [16u * 2 * 65536 * 32];
__device__ __half g_s_t [16 * 2 * 256 * 32];
__device__ __half g_cc_t[32 * 2 * 256 * 32];
__device__ __half g_h_t [16 * 2 * 256 * 32];
__device__ __half g_xe_t[16 * 2 * 512 * 32];
__device__ __half g_se_t[16 * 2 * 512 * 32];
__device__ __half g_hh_t[16 * 2 * 1536 * 32];
__device__ __half g_ih_t[32 * 2 * 1536 * 32];
__device__ __half g_fc_t[16 * 2 * 6656 * 32];

// ---------------- helpers ----------------
__device__ __forceinline__ uint32_t smem_u32(const void* p) {
    uint32_t a;
    asm("{ .reg .u64 t; cvta.to.shared.u64 t, %1; cvt.u32.u64 %0, t; }" : "=r"(a) : "l"(p));
    return a;
}
__device__ __forceinline__ void ldmx4(uint32_t addr, uint32_t* r) {
    asm volatile("ldmatrix.sync.aligned.m8n8.x4.shared.b16 {%0,%1,%2,%3}, [%4];"
        : "=r"(r[0]), "=r"(r[1]), "=r"(r[2]), "=r"(r[3]) : "r"(addr));
}
__device__ __forceinline__ void mma_f16(float* c, const uint32_t* a, uint32_t b0, uint32_t b1) {
    asm volatile("mma.sync.aligned.m16n8k16.row.col.f32.f16.f16.f32 "
        "{%0,%1,%2,%3}, {%4,%5,%6,%7}, {%8,%9}, {%0,%1,%2,%3};"
        : "+f"(c[0]), "+f"(c[1]), "+f"(c[2]), "+f"(c[3])
        : "r"(a[0]), "r"(a[1]), "r"(a[2]), "r"(a[3]), "r"(b0), "r"(b1));
}
#define MBAR_INIT(mb, c) asm volatile("mbarrier.init.shared.b64 [%0], %1;" :: "r"(mb), "r"(c) : "memory")
#define MB_EXPECT(mb, n) asm volatile("mbarrier.arrive.expect_tx.shared.b64 _, [%0], %1;" :: "r"(mb), "r"(n) : "memory")
#define FENCE_ASYNC()    asm volatile("fence.proxy.async.shared::cta;" ::: "memory")
#define BULK_G2S(dst, src, sz, mb) \
    asm volatile("cp.async.bulk.shared::cluster.global.mbarrier::complete_tx::bytes [%0], [%1], %2, [%3];" \
        :: "r"(dst), "l"(src), "r"(sz), "r"(mb) : "memory")

__device__ __forceinline__ void mbar_wait(uint32_t mb, uint32_t phase) {
    asm volatile(
        "{\n\t.reg .pred P;\n\t"
        "WL%=:\n\t"
        "mbarrier.try_wait.parity.acquire.cta.shared::cta.b64 P, [%0], %1, 0x989680;\n\t"
        "@!P bra WL%=;\n\t}"
        :: "r"(mb), "r"(phase) : "memory");
}

__device__ __forceinline__ float tanh_fast(float x) {
    float xc = fminf(fmaxf(x, -15.f), 15.f);
    float e = exp2f(xc * 2.8853900817779268f);
    return __fdividef(e - 1.0f, e + 1.0f);
}
__device__ __forceinline__ uint32_t pack_hi_lo(float a, float b, uint32_t& lo) {
    __half ha = __float2half_rn(a), hb = __float2half_rn(b);
    __half la = __float2half_rn(a - __half2float(ha));
    __half lb = __float2half_rn(b - __half2float(hb));
    lo = (uint32_t)*(unsigned short*)&la | ((uint32_t)*(unsigned short*)&lb << 16);
    return (uint32_t)*(unsigned short*)&ha | ((uint32_t)*(unsigned short*)&hb << 16);
}

// ---------------- split writers ----------------
template<bool LO>
__device__ __forceinline__ void split_unit(const float* __restrict__ w,
                                           __half* __restrict__ out,
                                           int Rpad, int K, int u)
{
    int upr = K >> 3;
    int r = u / upr, uu = u - r * upr;
    int c = uu >> 2, j = uu & 3;
    const float4* src = (const float4*)(w + (size_t)r * K + c * 32 + j * 8);
    float4 v0 = src[0], v1 = src[1];
    float f[8] = {v0.x, v0.y, v0.z, v0.w, v1.x, v1.y, v1.z, v1.w};
    uint32_t h[4], l[4];
    #pragma unroll
    for (int i = 0; i < 4; i++) h[i] = pack_hi_lo(f[2 * i], f[2 * i + 1], l[i]);
    size_t slab = ((size_t)(c * 2) * Rpad + r) * 32;
    uint32_t sw = (uint32_t)(j ^ ((r >> 1) & 3)) << 4;
    *(uint4*)((char*)(out + slab) + sw) = make_uint4(h[0], h[1], h[2], h[3]);
    if (LO)
        *(uint4*)((char*)(out + slab) + (size_t)Rpad * 64 + sw) = make_uint4(l[0], l[1], l[2], l[3]);
}

__global__ void split_gen(const float* __restrict__ w, __half* __restrict__ out,
                          int Rpad, int K, int nunits)
{
    int u = blockIdx.x * blockDim.x + threadIdx.x;
    if (u < nunits) split_unit<true>(w, out, Rpad, K, u);
}

#define Q_TOT 784448
__global__ void split_weights(const float* xe, const float* se, const float* hh,
                              const float* ih, const float* fc,
                              const float* se_b, const float* xe_b)
{
    int u = blockIdx.x * blockDim.x + threadIdx.x;
    if (u < 32768)  { split_unit<false>(xe, g_xe_t, 512, 512, u); return; }  u -= 32768;
    if (u < 32768)  { split_unit<false>(se, g_se_t, 512, 512, u); return; }  u -= 32768;
    if (u < 98304)  { split_unit<false>(hh, g_hh_t, 1536, 512, u); return; } u -= 98304;
    if (u < 196608) { split_unit<false>(ih, g_ih_t, 1536, 1024, u); return; } u -= 196608;
    if (u < 424000) { split_unit<false>(fc, g_fc_t, 6656, 512, u); return; } u -= 424000;
    if (u < 512)    { g_cbias[u] = se_b[u] + xe_b[u]; }
}

// tiled scalar-pair writer
__device__ __forceinline__ void store_pair_tiled(__half* base, int Rpad,
                                                 int r, int col, float v0, float v1)
{
    uint32_t lo, hi = pack_hi_lo(v0, v1, lo);
    int c = col >> 5, k = col & 31, j = k >> 3;
    size_t slab = ((size_t)(c * 2) * Rpad + r) * 32;
    uint32_t sw = ((uint32_t)(j ^ ((r >> 1) & 3)) << 4) + (k & 7) * 2;
    *(uint32_t*)((char*)(base + slab) + sw) = hi;
    *(uint32_t*)((char*)(base + slab) + (size_t)Rpad * 64 + sw) = lo;
}

// ============ small GEMM: M-tile 64, N-tile 128, 3 stages, 256 thr ============
#define STG_G   16384            // Ahi 4K | Alo 4K | Whi 8K
#define MB_G    (3 * STG_G)      // 49152
#define SMEM_G  (MB_G + 64)

__device__ __forceinline__ void issue64(uint32_t stbase, uint32_t mb,
        const __half* At, int RpadA, int m0,
        const __half* Wt, int RpadW, int nb, int chunk)
{
    MB_EXPECT(mb, 16384u);
    const char* a0 = (const char*)(At + ((size_t)(chunk * 2 + 0) * RpadA + m0) * 32);
    const char* a1 = (const char*)(At + ((size_t)(chunk * 2 + 1) * RpadA + m0) * 32);
    const char* w0 = (const char*)(Wt + ((size_t)(chunk * 2 + 0) * RpadW + nb) * 32);
    BULK_G2S(stbase,          a0, 4096u, mb);
    BULK_G2S(stbase + 4096,   a1, 4096u, mb);
    BULK_G2S(stbase + 8192,   w0, 8192u, mb);
}

// warp tile 32x32, 2-term fp16
__device__ __forceinline__ void cchunk64(uint32_t aB, uint32_t wB, int lane,
                                         int wm, int wn, float (&acc)[2][4][4])
{
    #pragma unroll
    for (int ks = 0; ks < 2; ++ks) {
        uint32_t Ah[2][4], Al[2][4];
        #pragma unroll
        for (int mt = 0; mt < 2; ++mt) {
            int row = wm + mt * 16 + (lane & 15);
            uint32_t col = (uint32_t)((ks * 2 + (lane >> 4)) ^ ((row >> 1) & 3));
            uint32_t off = (uint32_t)row * 64 + col * 16;
            ldmx4(aB + off, Ah[mt]);
            ldmx4(aB + 4096 + off, Al[mt]);
        }
        #pragma unroll
        for (int g = 0; g < 2; ++g) {
            int row = wn + g * 16 + ((lane >> 4) << 3) + (lane & 7);
            uint32_t col = (uint32_t)((ks * 2 + ((lane >> 3) & 1)) ^ ((row >> 1) & 3));
            uint32_t off = (uint32_t)row * 64 + col * 16;
            uint32_t bh[4];
            ldmx4(wB + off, bh);
            #pragma unroll
            for (int mt = 0; mt < 2; ++mt)
                #pragma unroll
                for (int h = 0; h < 2; ++h) {
                    float* c = acc[mt][g * 2 + h];
                    mma_f16(c, Ah[mt], bh[2 * h], bh[2 * h + 1]);
                    mma_f16(c, Al[mt], bh[2 * h], bh[2 * h + 1]);
                }
        }
    }
}

template<bool GUARD>
__global__ void __launch_bounds__(256, 1)
bulk_gemm(const __half* __restrict__ At, int RpadA,
          const __half* __restrict__ Wt, int RpadW,
          const float* __restrict__ bias, float* __restrict__ C, int N, int K)
{
    extern __shared__ char smc[];
    uint32_t sm = smem_u32(smc);
    int tid = threadIdx.x, lane = tid & 31, wid = tid >> 5;
    int wm = (wid >> 2) * 32, wn = (wid & 3) * 32;
    int m0 = blockIdx.y * 64, nb = blockIdx.x * 128;
    uint32_t mb = sm + MB_G;
    int NC = K >> 5;

    if (tid == 0) {
        for (int s = 0; s < 3; s++) MBAR_INIT(mb + 8 * s, 1);
    }
    __syncthreads();
    if (tid == 0) {
        FENCE_ASYNC();
        for (int s = 0; s < 3; s++)
            issue64(sm + s * STG_G, mb + 8 * s, At, RpadA, m0, Wt, RpadW, nb, s);
    }

    float acc[2][4][4] = {};
    for (int c = 0; c < NC; ++c) {
        int st = c % 3;
        mbar_wait(mb + 8 * st, (uint32_t)((c / 3) & 1));
        cchunk64(sm + st * STG_G, sm + st * STG_G + 8192, lane, wm, wn, acc);
        __syncthreads();
        if (tid == 0 && c + 3 < NC) {
            FENCE_ASYNC();
            issue64(sm + st * STG_G, mb + 8 * st, At, RpadA, m0, Wt, RpadW, nb, c + 3);
        }
    }

    #pragma unroll
    for (int mt = 0; mt < 2; ++mt) {
        int r1 = m0 + wm + mt * 16 + (lane >> 2), r2 = r1 + 8;
        #pragma unroll
        for (int nt = 0; nt < 4; ++nt) {
            int n = nb + wn + nt * 8 + 2 * (lane & 3);
            if (!GUARD || n < N) {
                float b0 = bias[n];
                C[(size_t)r1 * N + n] = acc[mt][nt][0] + b0;
                C[(size_t)r2 * N + n] = acc[mt][nt][2] + b0;
                if (!GUARD || n + 1 < N) {
                    float b1 = bias[n + 1];
                    C[(size_t)r1 * N + n + 1] = acc[mt][nt][1] + b1;
                    C[(size_t)r2 * N + n + 1] = acc[mt][nt][3] + b1;
                }
            }
        }
    }
}

// ============ persistent scores kernel: grid 148, 256 thr, tile 128x256 ============
#define STG_S   32768            // Ahi 8K | Alo 8K | Whi 16K
#define TAB_S   (3 * STG_S)      // 98304: we 2K | cbbuf 2K | part 2K
#define MB_S    (TAB_S + 6144)
#define SMEM_S  (MB_S + 64)
#define NTILES  1024
#define GRID_S  148

__device__ __forceinline__ void issue128(uint32_t stbase, uint32_t mb, int m0, int nb, int chunk)
{
    MB_EXPECT(mb, 32768u);
    const char* a0 = (const char*)(g_x_t + ((size_t)(chunk * 2 + 0) * 65536 + m0) * 32);
    const char* a1 = (const char*)(g_x_t + ((size_t)(chunk * 2 + 1) * 65536 + m0) * 32);
    const char* w0 = (const char*)(g_xe_t + ((size_t)(chunk * 2 + 0) * 512 + nb) * 32);
    BULK_G2S(stbase,          a0, 8192u,  mb);
    BULK_G2S(stbase + 8192,   a1, 8192u,  mb);
    BULK_G2S(stbase + 16384,  w0, 16384u, mb);
}

// warp tile 64x64, 2-term fp16
__device__ __forceinline__ void cchunk128(uint32_t aB, uint32_t wB, int lane,
                                          int wm, int wn, float (&acc)[4][8][4])
{
    #pragma unroll
    for (int ks = 0; ks < 2; ++ks) {
        uint32_t Ah[4][4], Al[4][4];
        #pragma unroll
        for (int mt = 0; mt < 4; ++mt) {
            int row = wm + mt * 16 + (lane & 15);
            uint32_t col = (uint32_t)((ks * 2 + (lane >> 4)) ^ ((row >> 1) & 3));
            uint32_t off = (uint32_t)row * 64 + col * 16;
            ldmx4(aB + off, Ah[mt]);
            ldmx4(aB + 8192 + off, Al[mt]);
        }
        #pragma unroll
        for (int g = 0; g < 4; ++g) {
            int row = wn + g * 16 + ((lane >> 4) << 3) + (lane & 7);
            uint32_t col = (uint32_t)((ks * 2 + ((lane >> 3) & 1)) ^ ((row >> 1) & 3));
            uint32_t off = (uint32_t)row * 64 + col * 16;
            uint32_t bh[4];
            ldmx4(wB + off, bh);
            #pragma unroll
            for (int mt = 0; mt < 4; ++mt)
                #pragma unroll
                for (int h = 0; h < 2; ++h) {
                    float* c = acc[mt][g * 2 + h];
                    mma_f16(c, Ah[mt], bh[2 * h], bh[2 * h + 1]);
                    mma_f16(c, Al[mt], bh[2 * h], bh[2 * h + 1]);
                }
        }
    }
}

__device__ __forceinline__ void issue_tile(uint32_t sm, uint32_t mb, int bid, int gq)
{
    int t = bid + (gq >> 4) * GRID_S;
    int chunk = gq & 15;
    int m0 = (t >> 1) << 7;
    int nb = (t & 1) << 8;
    int st = gq % 3;
    issue128(sm + st * STG_S, mb + 8 * st, m0, nb, chunk);
}

__global__ void __launch_bounds__(256, 1)
bulk_scores(const float* __restrict__ we)
{
    extern __shared__ char smc[];
    uint32_t sm = smem_u32(smc);
    int tid = threadIdx.x, lane = tid & 31, wid = tid >> 5;
    int wm = (wid >> 2) * 64, wn = (wid & 3) * 64;
    int wx = wid & 3;
    int bid = blockIdx.x;
    uint32_t mb = sm + MB_S;

    float* we_s  = (float*)(smc + TAB_S);        // 512
    float* cbbuf = we_s + 512;                   // 2 x 256
    float* part  = cbbuf + 512;                  // 512

    we_s[tid]       = we[tid];
    we_s[tid + 256] = we[tid + 256];

    int nt_cta = (NTILES - bid + GRID_S - 1) / GRID_S;
    int total = nt_cta * 16;

    if (tid == 0) {
        for (int s = 0; s < 3; s++) MBAR_INIT(mb + 8 * s, 1);
    }
    __syncthreads();
    if (tid == 0) {
        FENCE_ASYNC();
        for (int s = 0; s < 3; s++) issue_tile(sm, mb, bid, s);
    }

    float acc[4][8][4] = {};
    for (int gq = 0; gq < total; ++gq) {
        int tt = gq >> 4;
        int t  = bid + tt * GRID_S;
        if ((gq & 15) == 0) {
            int bidx = t >> 2;
            int nb   = (t & 1) << 8;
            cbbuf[(tt & 1) * 256 + tid] = g_sProj[bidx * 512 + nb + tid];
        }
        int st = gq % 3;
        mbar_wait(mb + 8 * st, (uint32_t)((gq / 3) & 1));
        cchunk128(sm + st * STG_S, sm + st * STG_S + 16384, lane, wm, wn, acc);
        __syncthreads();
        if (tid == 0 && gq + 3 < total) {
            FENCE_ASYNC();
            issue_tile(sm, mb, bid, gq + 3);
        }
        if ((gq & 15) == 15) {
            int m0 = (t >> 1) << 7;
            int nb = (t & 1) << 8;
            float* cb = cbbuf + (tt & 1) * 256;
            #pragma unroll
            for (int mt = 0; mt < 4; ++mt) {
                float s1 = 0.f, s2 = 0.f;
                #pragma unroll
                for (int ntc = 0; ntc < 8; ++ntc) {
                    int n = wn + ntc * 8 + 2 * (lane & 3);
                    float c0 = cb[n], c1 = cb[n + 1];
                    float w0 = we_s[nb + n], w1 = we_s[nb + n + 1];
                    s1 += tanh_fast(acc[mt][ntc][0] + c0) * w0 + tanh_fast(acc[mt][ntc][1] + c1) * w1;
                    s2 += tanh_fast(acc[mt][ntc][2] + c0) * w0 + tanh_fast(acc[mt][ntc][3] + c1) * w1;
                    acc[mt][ntc][0] = 0.f; acc[mt][ntc][1] = 0.f;
                    acc[mt][ntc][2] = 0.f; acc[mt][ntc][3] = 0.f;
                }
                s1 += __shfl_xor_sync(0xffffffffu, s1, 1); s1 += __shfl_xor_sync(0xffffffffu, s1, 2);
                s2 += __shfl_xor_sync(0xffffffffu, s2, 1); s2 += __shfl_xor_sync(0xffffffffu, s2, 2);
                if ((lane & 3) == 0) {
                    int rl = wm + mt * 16 + (lane >> 2);
                    part[wx * 128 + rl]     = s1;
                    part[wx * 128 + rl + 8] = s2;
                }
            }
            __syncthreads();
            if (tid < 128)
                g_spart[(t & 1) * 65536 + m0 + tid] =
                    part[tid] + part[128 + tid] + part[256 + tid] + part[384 + tid];
        }
    }
}

// ---------------- fused softmax + context + cc ----------------
__global__ void softmax_ctx_cc(const float* __restrict__ x,
                               const float* __restrict__ emb,
                               const int* __restrict__ yPrev)
{
    int b = blockIdx.x, t = threadIdx.x;
    __shared__ float al[T_];
    __shared__ float red[T_];
    float v = g_spart[b * 256 + t] + g_spart[65536 + b * 256 + t];
    red[t] = v; __syncthreads();
    for (int s = 128; s; s >>= 1) { if (t < s) red[t] = fmaxf(red[t], red[t + s]); __syncthreads(); }
    float mx = red[0]; __syncthreads();
    float e = expf(v - mx);
    red[t] = e; __syncthreads();
    for (int s = 128; s; s >>= 1) { if (t < s) red[t] += red[t + s]; __syncthreads(); }
    al[t] = e / red[0];
    __syncthreads();

    const float* xb = x + (size_t)b * 256 * 512;
    float c0 = 0.f, c1 = 0.f;
    #pragma unroll 4
    for (int tt = 0; tt < 256; ++tt) {
        float a = al[tt];
        float2 xv = *(const float2*)(xb + (size_t)tt * 512 + 2 * t);
        c0 += a * xv.x; c1 += a * xv.y;
    }
    store_pair_tiled(g_cc_t, 256, b, 512 + 2 * t, c0, c1);

    int y = yPrev[b];
    float2 ev = *(const float2*)(emb + (size_t)y * 512 + 2 * t);
    store_pair_tiled(g_cc_t, 256, b, 2 * t, ev.x, ev.y);
}

// ---------------- GRU elementwise ----------------
__global__ void gru_kernel(const float* __restrict__ s, float* __restrict__ h_out)
{
    int b = blockIdx.x, t = threadIdx.x;
    float hv[2];
    #pragma unroll
    for (int q = 0; q < 2; ++q) {
        int j = 2 * t + q;
        float ir = g_gi[b * 1536 + j];
        float iz = g_gi[b * 1536 + 512 + j];
        float in_ = g_gi[b * 1536 + 1024 + j];
        float hr = g_gh[b * 1536 + j];
        float hz = g_gh[b * 1536 + 512 + j];
        float hn = g_gh[b * 1536 + 1024 + j];
        float r = 1.f / (1.f + expf(-(ir + hr)));
        float z = 1.f / (1.f + expf(-(iz + hz)));
        float n = tanhf(in_ + r * hn);
        hv[q] = (1.f - z) * n + z * s[b * 512 + j];
        if (h_out) h_out[b * 512 + j] = hv[q];
    }
    store_pair_tiled(g_h_t, 256, b, 2 * t, hv[0], hv[1]);
}

// ======================================================================
extern "C" void kernel_launch(void* const* d_in, const int* in_sizes, int n_in,
                              void* d_out, int out_size)
{
    const float* x     = (const float*)d_in[0];
    const float* sPrev = (const float*)d_in[1];
    const int*   yPrev = (const int*)  d_in[2];
    const float* xe_w  = (const float*)d_in[3];
    const float* xe_b  = (const float*)d_in[4];
    const float* se_w  = (const float*)d_in[5];
    const float* se_b  = (const float*)d_in[6];
    const float* we_w  = (const float*)d_in[7];
    const float* emb   = (const float*)d_in[9];
    const float* w_ih  = (const float*)d_in[10];
    const float* w_hh  = (const float*)d_in[11];
    const float* b_ih  = (const float*)d_in[12];
    const float* b_hh  = (const float*)d_in[13];
    const float* fc_w  = (const float*)d_in[14];
    const float* fc_b  = (const float*)d_in[15];

    float* out = (float*)d_out;
    float* h_out = (out_size >= B_ * YD_ + B_ * 512) ? out + (size_t)B_ * YD_ : nullptr;

    float *sProj_p, *gi_p, *gh_p, *cbias_p;
    cudaGetSymbolAddress((void**)&sProj_p, g_sProj);
    cudaGetSymbolAddress((void**)&gi_p, g_gi);
    cudaGetSymbolAddress((void**)&gh_p, g_gh);
    cudaGetSymbolAddress((void**)&cbias_p, g_cbias);
    __half *x_t, *s_t, *cc_t, *h_t, *se_t, *hh_t, *ih_t, *fc_t;
    cudaGetSymbolAddress((void**)&x_t,  g_x_t);
    cudaGetSymbolAddress((void**)&s_t,  g_s_t);
    cudaGetSymbolAddress((void**)&cc_t, g_cc_t);
    cudaGetSymbolAddress((void**)&h_t,  g_h_t);
    cudaGetSymbolAddress((void**)&se_t, g_se_t);
    cudaGetSymbolAddress((void**)&hh_t, g_hh_t);
    cudaGetSymbolAddress((void**)&ih_t, g_ih_t);
    cudaGetSymbolAddress((void**)&fc_t, g_fc_t);

    static cudaStream_t s2 = nullptr;
    static cudaEvent_t evFork = nullptr, evW = nullptr, evX = nullptr, evGH = nullptr;
    if (!s2) {
        cudaFuncSetAttribute(bulk_scores,      cudaFuncAttributeMaxDynamicSharedMemorySize, SMEM_S);
        cudaFuncSetAttribute(bulk_gemm<false>, cudaFuncAttributeMaxDynamicSharedMemorySize, SMEM_G);
        cudaFuncSetAttribute(bulk_gemm<true>,  cudaFuncAttributeMaxDynamicSharedMemorySize, SMEM_G);
        cudaStreamCreateWithFlags(&s2, cudaStreamNonBlocking);
        cudaEventCreateWithFlags(&evFork, cudaEventDisableTiming);
        cudaEventCreateWithFlags(&evW, cudaEventDisableTiming);
        cudaEventCreateWithFlags(&evX, cudaEventDisableTiming);
        cudaEventCreateWithFlags(&evGH, cudaEventDisableTiming);
    }

    // ---- capture fork ----
    cudaEventRecord(evFork, 0);
    cudaStreamWaitEvent(s2, evFork, 0);

    // ---- stream 2: x split ----
    split_gen<<<16384, 256, 0, s2>>>(x, x_t, 65536, 512, 65536 * 64);
    cudaEventRecord(evX, s2);

    // ---- capture stream: s split, weight splits (+ cbias tail) ----
    split_gen<<<64, 256>>>(sPrev, s_t, 256, 512, 256 * 64);
    split_weights<<<(Q_TOT + 512 + 255) / 256, 256>>>(xe_w, se_w, w_hh, w_ih, fc_w, se_b, xe_b);
    cudaEventRecord(evW, 0);

    // gh on s2
    cudaStreamWaitEvent(s2, evW, 0);
    bulk_gemm<false><<<dim3(12, 4), 256, SMEM_G, s2>>>(s_t, 256, hh_t, 1536, b_hh, gh_p, 1536, 512);
    cudaEventRecord(evGH, s2);

    // ---- main chain ----
    bulk_gemm<false><<<dim3(4, 4), 256, SMEM_G>>>(s_t, 256, se_t, 512, cbias_p, sProj_p, 512, 512);
    cudaStreamWaitEvent(0, evX, 0);
    bulk_scores<<<GRID_S, 256, SMEM_S>>>(we_w);
    softmax_ctx_cc<<<256, 256>>>(x, emb, yPrev);
    bulk_gemm<false><<<dim3(12, 4), 256, SMEM_G>>>(cc_t, 256, ih_t, 1536, b_ih, gi_p, 1536, 1024);
    cudaStreamWaitEvent(0, evGH, 0);
    gru_kernel<<<256, 256>>>(sPrev, h_out);
    bulk_gemm<true><<<dim3(52, 4), 256, SMEM_G>>>(h_t, 256, fc_t, 6656, fc_b, out, 6625, 512);
}

// round 12
// speedup vs baseline: 1.8234x; 1.3517x over previous
#include <cuda_runtime.h>
#include <cuda_fp16.h>
#include <math.h>
#include <stdint.h>

#define B_  256
#define T_  256
#define YD_ 6625

// ---------------- fp32 scratch ----------------
__device__ float g_sProj[256 * 512];      // = s@se_w^T + (se_b + xe_b)
__device__ float g_spart[2 * 65536];
__device__ float g_gi[256 * 1536];
__device__ float g_gh[256 * 1536];
__device__ float g_cbias[512];

// ---------------- chunk-tiled, pre-swizzled fp16 scratch (hi plane only) ----
// slab(c) = base + c*Rpad*32 elems; row r at +r*32 elems (64B);
// within row, 16B unit j stored at (j ^ ((r>>1)&3)).
__device__ __half g_x_t [16u * 65536 * 32];
__device__ __half g_s_t [16 * 256 * 32];
__device__ __half g_cc_t[32 * 256 * 32];
__device__ __half g_h_t [16 * 256 * 32];
__device__ __half g_xe_t[16 * 512 * 32];
__device__ __half g_se_t[16 * 512 * 32];
__device__ __half g_hh_t[16 * 1536 * 32];
__device__ __half g_ih_t[32 * 1536 * 32];
__device__ __half g_fc_t[16 * 6656 * 32];

// ---------------- helpers ----------------
__device__ __forceinline__ uint32_t smem_u32(const void* p) {
    uint32_t a;
    asm("{ .reg .u64 t; cvta.to.shared.u64 t, %1; cvt.u32.u64 %0, t; }" : "=r"(a) : "l"(p));
    return a;
}
__device__ __forceinline__ void ldmx4(uint32_t addr, uint32_t* r) {
    asm volatile("ldmatrix.sync.aligned.m8n8.x4.shared.b16 {%0,%1,%2,%3}, [%4];"
        : "=r"(r[0]), "=r"(r[1]), "=r"(r[2]), "=r"(r[3]) : "r"(addr));
}
__device__ __forceinline__ void mma_f16(float* c, const uint32_t* a, uint32_t b0, uint32_t b1) {
    asm volatile("mma.sync.aligned.m16n8k16.row.col.f32.f16.f16.f32 "
        "{%0,%1,%2,%3}, {%4,%5,%6,%7}, {%8,%9}, {%0,%1,%2,%3};"
        : "+f"(c[0]), "+f"(c[1]), "+f"(c[2]), "+f"(c[3])
        : "r"(a[0]), "r"(a[1]), "r"(a[2]), "r"(a[3]), "r"(b0), "r"(b1));
}
#define MBAR_INIT(mb, c) asm volatile("mbarrier.init.shared.b64 [%0], %1;" :: "r"(mb), "r"(c) : "memory")
#define MB_EXPECT(mb, n) asm volatile("mbarrier.arrive.expect_tx.shared.b64 _, [%0], %1;" :: "r"(mb), "r"(n) : "memory")
#define FENCE_ASYNC()    asm volatile("fence.proxy.async.shared::cta;" ::: "memory")
#define BULK_G2S(dst, src, sz, mb) \
    asm volatile("cp.async.bulk.shared::cluster.global.mbarrier::complete_tx::bytes [%0], [%1], %2, [%3];" \
        :: "r"(dst), "l"(src), "r"(sz), "r"(mb) : "memory")

__device__ __forceinline__ void mbar_wait(uint32_t mb, uint32_t phase) {
    asm volatile(
        "{\n\t.reg .pred P;\n\t"
        "WL%=:\n\t"
        "mbarrier.try_wait.parity.acquire.cta.shared::cta.b64 P, [%0], %1, 0x989680;\n\t"
        "@!P bra WL%=;\n\t}"
        :: "r"(mb), "r"(phase) : "memory");
}

__device__ __forceinline__ float tanh_fast(float x) {
    float xc = fminf(fmaxf(x, -15.f), 15.f);
    float e = exp2f(xc * 2.8853900817779268f);
    return __fdividef(e - 1.0f, e + 1.0f);
}
__device__ __forceinline__ uint32_t pack_h2(float a, float b) {
    __half ha = __float2half_rn(a), hb = __float2half_rn(b);
    return (uint32_t)*(unsigned short*)&ha | ((uint32_t)*(unsigned short*)&hb << 16);
}

// ---------------- split writers (hi plane only) ----------------
__device__ __forceinline__ void split_unit(const float* __restrict__ w,
                                           __half* __restrict__ out,
                                           int Rpad, int K, int u)
{
    int upr = K >> 3;
    int r = u / upr, uu = u - r * upr;
    int c = uu >> 2, j = uu & 3;
    const float4* src = (const float4*)(w + (size_t)r * K + c * 32 + j * 8);
    float4 v0 = src[0], v1 = src[1];
    float f[8] = {v0.x, v0.y, v0.z, v0.w, v1.x, v1.y, v1.z, v1.w};
    uint32_t h[4];
    #pragma unroll
    for (int i = 0; i < 4; i++) h[i] = pack_h2(f[2 * i], f[2 * i + 1]);
    size_t slab = ((size_t)c * Rpad + r) * 32;
    uint32_t sw = (uint32_t)(j ^ ((r >> 1) & 3)) << 4;
    *(uint4*)((char*)(out + slab) + sw) = make_uint4(h[0], h[1], h[2], h[3]);
}

__global__ void split_gen(const float* __restrict__ w, __half* __restrict__ out,
                          int Rpad, int K, int nunits)
{
    int u = blockIdx.x * blockDim.x + threadIdx.x;
    if (u < nunits) split_unit(w, out, Rpad, K, u);
}

#define Q_TOT 784448
__global__ void split_weights(const float* xe, const float* se, const float* hh,
                              const float* ih, const float* fc,
                              const float* se_b, const float* xe_b)
{
    int u = blockIdx.x * blockDim.x + threadIdx.x;
    if (u < 32768)  { split_unit(xe, g_xe_t, 512, 512, u); return; }  u -= 32768;
    if (u < 32768)  { split_unit(se, g_se_t, 512, 512, u); return; }  u -= 32768;
    if (u < 98304)  { split_unit(hh, g_hh_t, 1536, 512, u); return; } u -= 98304;
    if (u < 196608) { split_unit(ih, g_ih_t, 1536, 1024, u); return; } u -= 196608;
    if (u < 424000) { split_unit(fc, g_fc_t, 6656, 512, u); return; } u -= 424000;
    if (u < 512)    { g_cbias[u] = se_b[u] + xe_b[u]; }
}

// tiled scalar-pair writer (hi only)
__device__ __forceinline__ void store_pair_tiled(__half* base, int Rpad,
                                                 int r, int col, float v0, float v1)
{
    uint32_t hi = pack_h2(v0, v1);
    int c = col >> 5, k = col & 31, j = k >> 3;
    size_t slab = ((size_t)c * Rpad + r) * 32;
    uint32_t sw = ((uint32_t)(j ^ ((r >> 1) & 3)) << 4) + (k & 7) * 2;
    *(uint32_t*)((char*)(base + slab) + sw) = hi;
}

// ============ small GEMM: M-tile 64, N-tile 128, 3 stages, 256 thr ============
#define STG_G   12288            // A 4K | W 8K
#define MB_G    (3 * STG_G)      // 36864
#define SMEM_G  (MB_G + 64)

__device__ __forceinline__ void issue64(uint32_t stbase, uint32_t mb,
        const __half* At, int RpadA, int m0,
        const __half* Wt, int RpadW, int nb, int chunk)
{
    MB_EXPECT(mb, 12288u);
    const char* a0 = (const char*)(At + ((size_t)chunk * RpadA + m0) * 32);
    const char* w0 = (const char*)(Wt + ((size_t)chunk * RpadW + nb) * 32);
    BULK_G2S(stbase,         a0, 4096u, mb);
    BULK_G2S(stbase + 4096,  w0, 8192u, mb);
}

// warp tile 32x32, 1-term fp16
__device__ __forceinline__ void cchunk64(uint32_t aB, uint32_t wB, int lane,
                                         int wm, int wn, float (&acc)[2][4][4])
{
    #pragma unroll
    for (int ks = 0; ks < 2; ++ks) {
        uint32_t Ah[2][4];
        #pragma unroll
        for (int mt = 0; mt < 2; ++mt) {
            int row = wm + mt * 16 + (lane & 15);
            uint32_t col = (uint32_t)((ks * 2 + (lane >> 4)) ^ ((row >> 1) & 3));
            ldmx4(aB + (uint32_t)row * 64 + col * 16, Ah[mt]);
        }
        #pragma unroll
        for (int g = 0; g < 2; ++g) {
            int row = wn + g * 16 + ((lane >> 4) << 3) + (lane & 7);
            uint32_t col = (uint32_t)((ks * 2 + ((lane >> 3) & 1)) ^ ((row >> 1) & 3));
            uint32_t bh[4];
            ldmx4(wB + (uint32_t)row * 64 + col * 16, bh);
            #pragma unroll
            for (int mt = 0; mt < 2; ++mt)
                #pragma unroll
                for (int h = 0; h < 2; ++h)
                    mma_f16(acc[mt][g * 2 + h], Ah[mt], bh[2 * h], bh[2 * h + 1]);
        }
    }
}

template<bool GUARD>
__global__ void __launch_bounds__(256, 1)
bulk_gemm(const __half* __restrict__ At, int RpadA,
          const __half* __restrict__ Wt, int RpadW,
          const float* __restrict__ bias, float* __restrict__ C, int N, int K)
{
    extern __shared__ char smc[];
    uint32_t sm = smem_u32(smc);
    int tid = threadIdx.x, lane = tid & 31, wid = tid >> 5;
    int wm = (wid >> 2) * 32, wn = (wid & 3) * 32;
    int m0 = blockIdx.y * 64, nb = blockIdx.x * 128;
    uint32_t mb = sm + MB_G;
    int NC = K >> 5;

    if (tid == 0) {
        for (int s = 0; s < 3; s++) MBAR_INIT(mb + 8 * s, 1);
    }
    __syncthreads();
    if (tid == 0) {
        FENCE_ASYNC();
        for (int s = 0; s < 3; s++)
            issue64(sm + s * STG_G, mb + 8 * s, At, RpadA, m0, Wt, RpadW, nb, s);
    }

    float acc[2][4][4] = {};
    for (int c = 0; c < NC; ++c) {
        int st = c % 3;
        mbar_wait(mb + 8 * st, (uint32_t)((c / 3) & 1));
        cchunk64(sm + st * STG_G, sm + st * STG_G + 4096, lane, wm, wn, acc);
        __syncthreads();
        if (tid == 0 && c + 3 < NC) {
            FENCE_ASYNC();
            issue64(sm + st * STG_G, mb + 8 * st, At, RpadA, m0, Wt, RpadW, nb, c + 3);
        }
    }

    #pragma unroll
    for (int mt = 0; mt < 2; ++mt) {
        int r1 = m0 + wm + mt * 16 + (lane >> 2), r2 = r1 + 8;
        #pragma unroll
        for (int nt = 0; nt < 4; ++nt) {
            int n = nb + wn + nt * 8 + 2 * (lane & 3);
            if (!GUARD || n < N) {
                float b0 = bias[n];
                C[(size_t)r1 * N + n] = acc[mt][nt][0] + b0;
                C[(size_t)r2 * N + n] = acc[mt][nt][2] + b0;
                if (!GUARD || n + 1 < N) {
                    float b1 = bias[n + 1];
                    C[(size_t)r1 * N + n + 1] = acc[mt][nt][1] + b1;
                    C[(size_t)r2 * N + n + 1] = acc[mt][nt][3] + b1;
                }
            }
        }
    }
}

// ============ persistent scores kernel: grid 148, 256 thr, tile 128x256 ============
#define STG_S   24576            // A 8K | W 16K
#define TAB_S   (3 * STG_S)      // 73728
#define MB_S    (TAB_S + 6144)
#define SMEM_S  (MB_S + 64)
#define NTILES  1024
#define GRID_S  148

__device__ __forceinline__ void issue128(uint32_t stbase, uint32_t mb, int m0, int nb, int chunk)
{
    MB_EXPECT(mb, 24576u);
    const char* a0 = (const char*)(g_x_t + ((size_t)chunk * 65536 + m0) * 32);
    const char* w0 = (const char*)(g_xe_t + ((size_t)chunk * 512 + nb) * 32);
    BULK_G2S(stbase,         a0, 8192u,  mb);
    BULK_G2S(stbase + 8192,  w0, 16384u, mb);
}

// warp tile 64x64, 1-term fp16
__device__ __forceinline__ void cchunk128(uint32_t aB, uint32_t wB, int lane,
                                          int wm, int wn, float (&acc)[4][8][4])
{
    #pragma unroll
    for (int ks = 0; ks < 2; ++ks) {
        uint32_t Ah[4][4];
        #pragma unroll
        for (int mt = 0; mt < 4; ++mt) {
            int row = wm + mt * 16 + (lane & 15);
            uint32_t col = (uint32_t)((ks * 2 + (lane >> 4)) ^ ((row >> 1) & 3));
            ldmx4(aB + (uint32_t)row * 64 + col * 16, Ah[mt]);
        }
        #pragma unroll
        for (int g = 0; g < 4; ++g) {
            int row = wn + g * 16 + ((lane >> 4) << 3) + (lane & 7);
            uint32_t col = (uint32_t)((ks * 2 + ((lane >> 3) & 1)) ^ ((row >> 1) & 3));
            uint32_t bh[4];
            ldmx4(wB + (uint32_t)row * 64 + col * 16, bh);
            #pragma unroll
            for (int mt = 0; mt < 4; ++mt)
                #pragma unroll
                for (int h = 0; h < 2; ++h)
                    mma_f16(acc[mt][g * 2 + h], Ah[mt], bh[2 * h], bh[2 * h + 1]);
        }
    }
}

__device__ __forceinline__ void issue_tile(uint32_t sm, uint32_t mb, int bid, int gq)
{
    int t = bid + (gq >> 4) * GRID_S;
    int chunk = gq & 15;
    int m0 = (t >> 1) << 7;
    int nb = (t & 1) << 8;
    int st = gq % 3;
    issue128(sm + st * STG_S, mb + 8 * st, m0, nb, chunk);
}

__global__ void __launch_bounds__(256, 1)
bulk_scores(const float* __restrict__ we)
{
    extern __shared__ char smc[];
    uint32_t sm = smem_u32(smc);
    int tid = threadIdx.x, lane = tid & 31, wid = tid >> 5;
    int wm = (wid >> 2) * 64, wn = (wid & 3) * 64;
    int wx = wid & 3;
    int bid = blockIdx.x;
    uint32_t mb = sm + MB_S;

    float* we_s  = (float*)(smc + TAB_S);        // 512
    float* cbbuf = we_s + 512;                   // 2 x 256
    float* part  = cbbuf + 512;                  // 512

    we_s[tid]       = we[tid];
    we_s[tid + 256] = we[tid + 256];

    int nt_cta = (NTILES - bid + GRID_S - 1) / GRID_S;
    int total = nt_cta * 16;

    if (tid == 0) {
        for (int s = 0; s < 3; s++) MBAR_INIT(mb + 8 * s, 1);
    }
    __syncthreads();
    if (tid == 0) {
        FENCE_ASYNC();
        for (int s = 0; s < 3; s++) issue_tile(sm, mb, bid, s);
    }

    float acc[4][8][4] = {};
    for (int gq = 0; gq < total; ++gq) {
        int tt = gq >> 4;
        int t  = bid + tt * GRID_S;
        if ((gq & 15) == 0) {
            int bidx = t >> 2;
            int nb   = (t & 1) << 8;
            cbbuf[(tt & 1) * 256 + tid] = g_sProj[bidx * 512 + nb + tid];
        }
        int st = gq % 3;
        mbar_wait(mb + 8 * st, (uint32_t)((gq / 3) & 1));
        cchunk128(sm + st * STG_S, sm + st * STG_S + 8192, lane, wm, wn, acc);
        __syncthreads();
        if (tid == 0 && gq + 3 < total) {
            FENCE_ASYNC();
            issue_tile(sm, mb, bid, gq + 3);
        }
        if ((gq & 15) == 15) {
            int m0 = (t >> 1) << 7;
            int nb = (t & 1) << 8;
            float* cb = cbbuf + (tt & 1) * 256;
            #pragma unroll
            for (int mt = 0; mt < 4; ++mt) {
                float s1 = 0.f, s2 = 0.f;
                #pragma unroll
                for (int ntc = 0; ntc < 8; ++ntc) {
                    int n = wn + ntc * 8 + 2 * (lane & 3);
                    float c0 = cb[n], c1 = cb[n + 1];
                    float w0 = we_s[nb + n], w1 = we_s[nb + n + 1];
                    s1 += tanh_fast(acc[mt][ntc][0] + c0) * w0 + tanh_fast(acc[mt][ntc][1] + c1) * w1;
                    s2 += tanh_fast(acc[mt][ntc][2] + c0) * w0 + tanh_fast(acc[mt][ntc][3] + c1) * w1;
                    acc[mt][ntc][0] = 0.f; acc[mt][ntc][1] = 0.f;
                    acc[mt][ntc][2] = 0.f; acc[mt][ntc][3] = 0.f;
                }
                s1 += __shfl_xor_sync(0xffffffffu, s1, 1); s1 += __shfl_xor_sync(0xffffffffu, s1, 2);
                s2 += __shfl_xor_sync(0xffffffffu, s2, 1); s2 += __shfl_xor_sync(0xffffffffu, s2, 2);
                if ((lane & 3) == 0) {
                    int rl = wm + mt * 16 + (lane >> 2);
                    part[wx * 128 + rl]     = s1;
                    part[wx * 128 + rl + 8] = s2;
                }
            }
            __syncthreads();
            if (tid < 128)
                g_spart[(t & 1) * 65536 + m0 + tid] =
                    part[tid] + part[128 + tid] + part[256 + tid] + part[384 + tid];
        }
    }
}

// ---------------- fused softmax + context + cc ----------------
__global__ void softmax_ctx_cc(const float* __restrict__ x,
                               const float* __restrict__ emb,
                               const int* __restrict__ yPrev)
{
    int b = blockIdx.x, t = threadIdx.x;
    __shared__ float al[T_];
    __shared__ float red[T_];
    float v = g_spart[b * 256 + t] + g_spart[65536 + b * 256 + t];
    red[t] = v; __syncthreads();
    for (int s = 128; s; s >>= 1) { if (t < s) red[t] = fmaxf(red[t], red[t + s]); __syncthreads(); }
    float mx = red[0]; __syncthreads();
    float e = expf(v - mx);
    red[t] = e; __syncthreads();
    for (int s = 128; s; s >>= 1) { if (t < s) red[t] += red[t + s]; __syncthreads(); }
    al[t] = e / red[0];
    __syncthreads();

    const float* xb = x + (size_t)b * 256 * 512;
    float c0 = 0.f, c1 = 0.f;
    #pragma unroll 4
    for (int tt = 0; tt < 256; ++tt) {
        float a = al[tt];
        float2 xv = *(const float2*)(xb + (size_t)tt * 512 + 2 * t);
        c0 += a * xv.x; c1 += a * xv.y;
    }
    store_pair_tiled(g_cc_t, 256, b, 512 + 2 * t, c0, c1);

    int y = yPrev[b];
    float2 ev = *(const float2*)(emb + (size_t)y * 512 + 2 * t);
    store_pair_tiled(g_cc_t, 256, b, 2 * t, ev.x, ev.y);
}

// ---------------- GRU elementwise ----------------
__global__ void gru_kernel(const float* __restrict__ s, float* __restrict__ h_out)
{
    int b = blockIdx.x, t = threadIdx.x;
    float hv[2];
    #pragma unroll
    for (int q = 0; q < 2; ++q) {
        int j = 2 * t + q;
        float ir = g_gi[b * 1536 + j];
        float iz = g_gi[b * 1536 + 512 + j];
        float in_ = g_gi[b * 1536 + 1024 + j];
        float hr = g_gh[b * 1536 + j];
        float hz = g_gh[b * 1536 + 512 + j];
        float hn = g_gh[b * 1536 + 1024 + j];
        float r = 1.f / (1.f + expf(-(ir + hr)));
        float z = 1.f / (1.f + expf(-(iz + hz)));
        float n = tanhf(in_ + r * hn);
        hv[q] = (1.f - z) * n + z * s[b * 512 + j];
        if (h_out) h_out[b * 512 + j] = hv[q];
    }
    store_pair_tiled(g_h_t, 256, b, 2 * t, hv[0], hv[1]);
}

// ======================================================================
extern "C" void kernel_launch(void* const* d_in, const int* in_sizes, int n_in,
                              void* d_out, int out_size)
{
    const float* x     = (const float*)d_in[0];
    const float* sPrev = (const float*)d_in[1];
    const int*   yPrev = (const int*)  d_in[2];
    const float* xe_w  = (const float*)d_in[3];
    const float* xe_b  = (const float*)d_in[4];
    const float* se_w  = (const float*)d_in[5];
    const float* se_b  = (const float*)d_in[6];
    const float* we_w  = (const float*)d_in[7];
    const float* emb   = (const float*)d_in[9];
    const float* w_ih  = (const float*)d_in[10];
    const float* w_hh  = (const float*)d_in[11];
    const float* b_ih  = (const float*)d_in[12];
    const float* b_hh  = (const float*)d_in[13];
    const float* fc_w  = (const float*)d_in[14];
    const float* fc_b  = (const float*)d_in[15];

    float* out = (float*)d_out;
    float* h_out = (out_size >= B_ * YD_ + B_ * 512) ? out + (size_t)B_ * YD_ : nullptr;

    float *sProj_p, *gi_p, *gh_p, *cbias_p;
    cudaGetSymbolAddress((void**)&sProj_p, g_sProj);
    cudaGetSymbolAddress((void**)&gi_p, g_gi);
    cudaGetSymbolAddress((void**)&gh_p, g_gh);
    cudaGetSymbolAddress((void**)&cbias_p, g_cbias);
    __half *x_t, *s_t, *cc_t, *h_t, *se_t, *hh_t, *ih_t, *fc_t;
    cudaGetSymbolAddress((void**)&x_t,  g_x_t);
    cudaGetSymbolAddress((void**)&s_t,  g_s_t);
    cudaGetSymbolAddress((void**)&cc_t, g_cc_t);
    cudaGetSymbolAddress((void**)&h_t,  g_h_t);
    cudaGetSymbolAddress((void**)&se_t, g_se_t);
    cudaGetSymbolAddress((void**)&hh_t, g_hh_t);
    cudaGetSymbolAddress((void**)&ih_t, g_ih_t);
    cudaGetSymbolAddress((void**)&fc_t, g_fc_t);

    static cudaStream_t s2 = nullptr;
    static cudaEvent_t evFork = nullptr, evW = nullptr, evX = nullptr, evGH = nullptr;
    if (!s2) {
        cudaFuncSetAttribute(bulk_scores,      cudaFuncAttributeMaxDynamicSharedMemorySize, SMEM_S);
        cudaFuncSetAttribute(bulk_gemm<false>, cudaFuncAttributeMaxDynamicSharedMemorySize, SMEM_G);
        cudaFuncSetAttribute(bulk_gemm<true>,  cudaFuncAttributeMaxDynamicSharedMemorySize, SMEM_G);
        cudaStreamCreateWithFlags(&s2, cudaStreamNonBlocking);
        cudaEventCreateWithFlags(&evFork, cudaEventDisableTiming);
        cudaEventCreateWithFlags(&evW, cudaEventDisableTiming);
        cudaEventCreateWithFlags(&evX, cudaEventDisableTiming);
        cudaEventCreateWithFlags(&evGH, cudaEventDisableTiming);
    }

    // ---- capture fork ----
    cudaEventRecord(evFork, 0);
    cudaStreamWaitEvent(s2, evFork, 0);

    // ---- stream 2: x split ----
    split_gen<<<16384, 256, 0, s2>>>(x, x_t, 65536, 512, 65536 * 64);
    cudaEventRecord(evX, s2);

    // ---- capture stream: s split, weight splits (+ cbias tail) ----
    split_gen<<<64, 256>>>(sPrev, s_t, 256, 512, 256 * 64);
    split_weights<<<(Q_TOT + 512 + 255) / 256, 256>>>(xe_w, se_w, w_hh, w_ih, fc_w, se_b, xe_b);
    cudaEventRecord(evW, 0);

    // gh on s2
    cudaStreamWaitEvent(s2, evW, 0);
    bulk_gemm<false><<<dim3(12, 4), 256, SMEM_G, s2>>>(s_t, 256, hh_t, 1536, b_hh, gh_p, 1536, 512);
    cudaEventRecord(evGH, s2);

    // ---- main chain ----
    bulk_gemm<false><<<dim3(4, 4), 256, SMEM_G>>>(s_t, 256, se_t, 512, cbias_p, sProj_p, 512, 512);
    cudaStreamWaitEvent(0, evX, 0);
    bulk_scores<<<GRID_S, 256, SMEM_S>>>(we_w);
    softmax_ctx_cc<<<256, 256>>>(x, emb, yPrev);
    bulk_gemm<false><<<dim3(12, 4), 256, SMEM_G>>>(cc_t, 256, ih_t, 1536, b_ih, gi_p, 1536, 1024);
    cudaStreamWaitEvent(0, evGH, 0);
    gru_kernel<<<256, 256>>>(sPrev, h_out);
    bulk_gemm<true><<<dim3(52, 4), 256, SMEM_G>>>(h_t, 256, fc_t, 6656, fc_b, out, 6625, 512);
}

// round 13
// speedup vs baseline: 1.8584x; 1.0192x over previous
#include <cuda_runtime.h>
#include <cuda_fp16.h>
#include <math.h>
#include <stdint.h>

#define B_  256
#define T_  256
#define YD_ 6625

// ---------------- fp32 scratch ----------------
__device__ float g_sProj[256 * 512];      // = s@se_w^T + (se_b + xe_b)
__device__ float g_spart[2 * 65536];
__device__ float g_gi[256 * 1536];
__device__ float g_gh[256 * 1536];
__device__ float g_cbias[512];
__device__ int   g_xprog[512];            // per-128-row-block x-split progress

// ---------------- chunk-tiled, pre-swizzled fp16 scratch (hi plane only) ----
// slab(c) = base + c*Rpad*32 elems; row r at +r*32 elems (64B);
// within row, 16B unit j stored at (j ^ ((r>>1)&3)).
__device__ __half g_x_t [16u * 65536 * 32];
__device__ __half g_s_t [16 * 256 * 32];
__device__ __half g_cc_t[32 * 256 * 32];
__device__ __half g_h_t [16 * 256 * 32];
__device__ __half g_xe_t[16 * 512 * 32];
__device__ __half g_se_t[16 * 512 * 32];
__device__ __half g_hh_t[16 * 1536 * 32];
__device__ __half g_ih_t[32 * 1536 * 32];
__device__ __half g_fc_t[16 * 6656 * 32];

// ---------------- helpers ----------------
__device__ __forceinline__ uint32_t smem_u32(const void* p) {
    uint32_t a;
    asm("{ .reg .u64 t; cvta.to.shared.u64 t, %1; cvt.u32.u64 %0, t; }" : "=r"(a) : "l"(p));
    return a;
}
__device__ __forceinline__ void ldmx4(uint32_t addr, uint32_t* r) {
    asm volatile("ldmatrix.sync.aligned.m8n8.x4.shared.b16 {%0,%1,%2,%3}, [%4];"
        : "=r"(r[0]), "=r"(r[1]), "=r"(r[2]), "=r"(r[3]) : "r"(addr));
}
__device__ __forceinline__ void mma_f16(float* c, const uint32_t* a, uint32_t b0, uint32_t b1) {
    asm volatile("mma.sync.aligned.m16n8k16.row.col.f32.f16.f16.f32 "
        "{%0,%1,%2,%3}, {%4,%5,%6,%7}, {%8,%9}, {%0,%1,%2,%3};"
        : "+f"(c[0]), "+f"(c[1]), "+f"(c[2]), "+f"(c[3])
        : "r"(a[0]), "r"(a[1]), "r"(a[2]), "r"(a[3]), "r"(b0), "r"(b1));
}
#define MBAR_INIT(mb, c) asm volatile("mbarrier.init.shared.b64 [%0], %1;" :: "r"(mb), "r"(c) : "memory")
#define MB_EXPECT(mb, n) asm volatile("mbarrier.arrive.expect_tx.shared.b64 _, [%0], %1;" :: "r"(mb), "r"(n) : "memory")
#define FENCE_ASYNC()    asm volatile("fence.proxy.async.shared::cta;" ::: "memory")
#define BULK_G2S(dst, src, sz, mb) \
    asm volatile("cp.async.bulk.shared::cluster.global.mbarrier::complete_tx::bytes [%0], [%1], %2, [%3];" \
        :: "r"(dst), "l"(src), "r"(sz), "r"(mb) : "memory")

__device__ __forceinline__ void mbar_wait(uint32_t mb, uint32_t phase) {
    asm volatile(
        "{\n\t.reg .pred P;\n\t"
        "WL%=:\n\t"
        "mbarrier.try_wait.parity.acquire.cta.shared::cta.b64 P, [%0], %1, 0x989680;\n\t"
        "@!P bra WL%=;\n\t}"
        :: "r"(mb), "r"(phase) : "memory");
}

__device__ __forceinline__ float tanh_fast(float x) {
    float xc = fminf(fmaxf(x, -15.f), 15.f);
    float e = exp2f(xc * 2.8853900817779268f);
    return __fdividef(e - 1.0f, e + 1.0f);
}
__device__ __forceinline__ uint32_t pack_h2(float a, float b) {
    __half ha = __float2half_rn(a), hb = __float2half_rn(b);
    return (uint32_t)*(unsigned short*)&ha | ((uint32_t)*(unsigned short*)&hb << 16);
}

// ---------------- split writers (hi plane only) ----------------
__device__ __forceinline__ void split_unit(const float* __restrict__ w,
                                           __half* __restrict__ out,
                                           int Rpad, int K, int u)
{
    int upr = K >> 3;
    int r = u / upr, uu = u - r * upr;
    int c = uu >> 2, j = uu & 3;
    const float4* src = (const float4*)(w + (size_t)r * K + c * 32 + j * 8);
    float4 v0 = src[0], v1 = src[1];
    float f[8] = {v0.x, v0.y, v0.z, v0.w, v1.x, v1.y, v1.z, v1.w};
    uint32_t h[4];
    #pragma unroll
    for (int i = 0; i < 4; i++) h[i] = pack_h2(f[2 * i], f[2 * i + 1]);
    size_t slab = ((size_t)c * Rpad + r) * 32;
    uint32_t sw = (uint32_t)(j ^ ((r >> 1) & 3)) << 4;
    *(uint4*)((char*)(out + slab) + sw) = make_uint4(h[0], h[1], h[2], h[3]);
}

__global__ void split_gen(const float* __restrict__ w, __half* __restrict__ out,
                          int Rpad, int K, int nunits)
{
    int u = blockIdx.x * blockDim.x + threadIdx.x;
    if (u < nunits) split_unit(w, out, Rpad, K, u);
}

// x split with per-block progress publication (CTA covers rows b*4..b*4+3)
__global__ void split_x(const float* __restrict__ x)
{
    int u = blockIdx.x * 256 + threadIdx.x;
    split_unit(x, g_x_t, 65536, 512, u);
    __syncthreads();
    if (threadIdx.x == 0) {
        __threadfence();
        atomicAdd(&g_xprog[blockIdx.x >> 5], 1);
    }
}

__global__ void zero_prog()
{
    g_xprog[threadIdx.x + blockIdx.x * 256] = 0;
}

#define Q_TOT 784448
__global__ void split_weights(const float* xe, const float* se, const float* hh,
                              const float* ih, const float* fc,
                              const float* se_b, const float* xe_b)
{
    int u = blockIdx.x * blockDim.x + threadIdx.x;
    if (u < 32768)  { split_unit(xe, g_xe_t, 512, 512, u); return; }  u -= 32768;
    if (u < 32768)  { split_unit(se, g_se_t, 512, 512, u); return; }  u -= 32768;
    if (u < 98304)  { split_unit(hh, g_hh_t, 1536, 512, u); return; } u -= 98304;
    if (u < 196608) { split_unit(ih, g_ih_t, 1536, 1024, u); return; } u -= 196608;
    if (u < 424000) { split_unit(fc, g_fc_t, 6656, 512, u); return; } u -= 424000;
    if (u < 512)    { g_cbias[u] = se_b[u] + xe_b[u]; }
}

// tiled scalar-pair writer (hi only)
__device__ __forceinline__ void store_pair_tiled(__half* base, int Rpad,
                                                 int r, int col, float v0, float v1)
{
    uint32_t hi = pack_h2(v0, v1);
    int c = col >> 5, k = col & 31, j = k >> 3;
    size_t slab = ((size_t)c * Rpad + r) * 32;
    uint32_t sw = ((uint32_t)(j ^ ((r >> 1) & 3)) << 4) + (k & 7) * 2;
    *(uint32_t*)((char*)(base + slab) + sw) = hi;
}
// tiled pair reader
__device__ __forceinline__ float2 load_pair_tiled(const __half* base, int Rpad,
                                                  int r, int col)
{
    int c = col >> 5, k = col & 31, j = k >> 3;
    size_t slab = ((size_t)c * Rpad + r) * 32;
    uint32_t sw = ((uint32_t)(j ^ ((r >> 1) & 3)) << 4) + (k & 7) * 2;
    __half2 v = *(const __half2*)((const char*)(base + slab) + sw);
    return __half22float2(v);
}

// ============ small GEMM: M-tile 64, N-tile 128, 3 stages, 256 thr ============
#define STG_G   12288            // A 4K | W 8K
#define MB_G    (3 * STG_G)
#define SMEM_G  (MB_G + 64)

__device__ __forceinline__ void issue64(uint32_t stbase, uint32_t mb,
        const __half* At, int RpadA, int m0,
        const __half* Wt, int RpadW, int nb, int chunk)
{
    MB_EXPECT(mb, 12288u);
    const char* a0 = (const char*)(At + ((size_t)chunk * RpadA + m0) * 32);
    const char* w0 = (const char*)(Wt + ((size_t)chunk * RpadW + nb) * 32);
    BULK_G2S(stbase,         a0, 4096u, mb);
    BULK_G2S(stbase + 4096,  w0, 8192u, mb);
}

__device__ __forceinline__ void cchunk64(uint32_t aB, uint32_t wB, int lane,
                                         int wm, int wn, float (&acc)[2][4][4])
{
    #pragma unroll
    for (int ks = 0; ks < 2; ++ks) {
        uint32_t Ah[2][4];
        #pragma unroll
        for (int mt = 0; mt < 2; ++mt) {
            int row = wm + mt * 16 + (lane & 15);
            uint32_t col = (uint32_t)((ks * 2 + (lane >> 4)) ^ ((row >> 1) & 3));
            ldmx4(aB + (uint32_t)row * 64 + col * 16, Ah[mt]);
        }
        #pragma unroll
        for (int g = 0; g < 2; ++g) {
            int row = wn + g * 16 + ((lane >> 4) << 3) + (lane & 7);
            uint32_t col = (uint32_t)((ks * 2 + ((lane >> 3) & 1)) ^ ((row >> 1) & 3));
            uint32_t bh[4];
            ldmx4(wB + (uint32_t)row * 64 + col * 16, bh);
            #pragma unroll
            for (int mt = 0; mt < 2; ++mt)
                #pragma unroll
                for (int h = 0; h < 2; ++h)
                    mma_f16(acc[mt][g * 2 + h], Ah[mt], bh[2 * h], bh[2 * h + 1]);
        }
    }
}

template<bool GUARD>
__global__ void __launch_bounds__(256, 1)
bulk_gemm(const __half* __restrict__ At, int RpadA,
          const __half* __restrict__ Wt, int RpadW,
          const float* __restrict__ bias, float* __restrict__ C, int N, int K)
{
    extern __shared__ char smc[];
    uint32_t sm = smem_u32(smc);
    int tid = threadIdx.x, lane = tid & 31, wid = tid >> 5;
    int wm = (wid >> 2) * 32, wn = (wid & 3) * 32;
    int m0 = blockIdx.y * 64, nb = blockIdx.x * 128;
    uint32_t mb = sm + MB_G;
    int NC = K >> 5;

    if (tid == 0) {
        for (int s = 0; s < 3; s++) MBAR_INIT(mb + 8 * s, 1);
    }
    __syncthreads();
    if (tid == 0) {
        FENCE_ASYNC();
        for (int s = 0; s < 3; s++)
            issue64(sm + s * STG_G, mb + 8 * s, At, RpadA, m0, Wt, RpadW, nb, s);
    }

    float acc[2][4][4] = {};
    for (int c = 0; c < NC; ++c) {
        int st = c % 3;
        mbar_wait(mb + 8 * st, (uint32_t)((c / 3) & 1));
        cchunk64(sm + st * STG_G, sm + st * STG_G + 4096, lane, wm, wn, acc);
        __syncthreads();
        if (tid == 0 && c + 3 < NC) {
            FENCE_ASYNC();
            issue64(sm + st * STG_G, mb + 8 * st, At, RpadA, m0, Wt, RpadW, nb, c + 3);
        }
    }

    #pragma unroll
    for (int mt = 0; mt < 2; ++mt) {
        int r1 = m0 + wm + mt * 16 + (lane >> 2), r2 = r1 + 8;
        #pragma unroll
        for (int nt = 0; nt < 4; ++nt) {
            int n = nb + wn + nt * 8 + 2 * (lane & 3);
            if (!GUARD || n < N) {
                float b0 = bias[n];
                C[(size_t)r1 * N + n] = acc[mt][nt][0] + b0;
                C[(size_t)r2 * N + n] = acc[mt][nt][2] + b0;
                if (!GUARD || n + 1 < N) {
                    float b1 = bias[n + 1];
                    C[(size_t)r1 * N + n + 1] = acc[mt][nt][1] + b1;
                    C[(size_t)r2 * N + n + 1] = acc[mt][nt][3] + b1;
                }
            }
        }
    }
}

// ============ persistent scores kernel: grid 148, 256 thr, tile 128x256 ============
#define STG_S   24576            // A 8K | W 16K
#define TAB_S   (3 * STG_S)
#define MB_S    (TAB_S + 6144)
#define SMEM_S  (MB_S + 64)
#define NTILES  1024
#define GRID_S  148

__device__ __forceinline__ void issue128(uint32_t stbase, uint32_t mb, int m0, int nb, int chunk)
{
    MB_EXPECT(mb, 24576u);
    const char* a0 = (const char*)(g_x_t + ((size_t)chunk * 65536 + m0) * 32);
    const char* w0 = (const char*)(g_xe_t + ((size_t)chunk * 512 + nb) * 32);
    BULK_G2S(stbase,         a0, 8192u,  mb);
    BULK_G2S(stbase + 8192,  w0, 16384u, mb);
}

__device__ __forceinline__ void cchunk128(uint32_t aB, uint32_t wB, int lane,
                                          int wm, int wn, float (&acc)[4][8][4])
{
    #pragma unroll
    for (int ks = 0; ks < 2; ++ks) {
        uint32_t Ah[4][4];
        #pragma unroll
        for (int mt = 0; mt < 4; ++mt) {
            int row = wm + mt * 16 + (lane & 15);
            uint32_t col = (uint32_t)((ks * 2 + (lane >> 4)) ^ ((row >> 1) & 3));
            ldmx4(aB + (uint32_t)row * 64 + col * 16, Ah[mt]);
        }
        #pragma unroll
        for (int g = 0; g < 4; ++g) {
            int row = wn + g * 16 + ((lane >> 4) << 3) + (lane & 7);
            uint32_t col = (uint32_t)((ks * 2 + ((lane >> 3) & 1)) ^ ((row >> 1) & 3));
            uint32_t bh[4];
            ldmx4(wB + (uint32_t)row * 64 + col * 16, bh);
            #pragma unroll
            for (int mt = 0; mt < 4; ++mt)
                #pragma unroll
                for (int h = 0; h < 2; ++h)
                    mma_f16(acc[mt][g * 2 + h], Ah[mt], bh[2 * h], bh[2 * h + 1]);
        }
    }
}

__device__ __forceinline__ void issue_tile(uint32_t sm, uint32_t mb, int bid, int gq)
{
    int t = bid + (gq >> 4) * GRID_S;
    int chunk = gq & 15;
    if (chunk == 0) {
        // wait until this tile's 128 x-rows are split (32 producer CTAs)
        volatile int* p = &g_xprog[t >> 1];
        while (*p < 32) { }
    }
    int m0 = (t >> 1) << 7;
    int nb = (t & 1) << 8;
    int st = gq % 3;
    issue128(sm + st * STG_S, mb + 8 * st, m0, nb, chunk);
}

__global__ void __launch_bounds__(256, 1)
bulk_scores(const float* __restrict__ we)
{
    extern __shared__ char smc[];
    uint32_t sm = smem_u32(smc);
    int tid = threadIdx.x, lane = tid & 31, wid = tid >> 5;
    int wm = (wid >> 2) * 64, wn = (wid & 3) * 64;
    int wx = wid & 3;
    int bid = blockIdx.x;
    uint32_t mb = sm + MB_S;

    float* we_s  = (float*)(smc + TAB_S);        // 512
    float* cbbuf = we_s + 512;                   // 2 x 256
    float* part  = cbbuf + 512;                  // 512

    we_s[tid]       = we[tid];
    we_s[tid + 256] = we[tid + 256];

    int nt_cta = (NTILES - bid + GRID_S - 1) / GRID_S;
    int total = nt_cta * 16;

    if (tid == 0) {
        for (int s = 0; s < 3; s++) MBAR_INIT(mb + 8 * s, 1);
    }
    __syncthreads();
    if (tid == 0) {
        FENCE_ASYNC();
        for (int s = 0; s < 3; s++) issue_tile(sm, mb, bid, s);
    }

    float acc[4][8][4] = {};
    for (int gq = 0; gq < total; ++gq) {
        int tt = gq >> 4;
        int t  = bid + tt * GRID_S;
        if ((gq & 15) == 0) {
            int bidx = t >> 2;
            int nb   = (t & 1) << 8;
            cbbuf[(tt & 1) * 256 + tid] = g_sProj[bidx * 512 + nb + tid];
        }
        int st = gq % 3;
        mbar_wait(mb + 8 * st, (uint32_t)((gq / 3) & 1));
        cchunk128(sm + st * STG_S, sm + st * STG_S + 8192, lane, wm, wn, acc);
        __syncthreads();
        if (tid == 0 && gq + 3 < total) {
            FENCE_ASYNC();
            issue_tile(sm, mb, bid, gq + 3);
        }
        if ((gq & 15) == 15) {
            int m0 = (t >> 1) << 7;
            int nb = (t & 1) << 8;
            float* cb = cbbuf + (tt & 1) * 256;
            #pragma unroll
            for (int mt = 0; mt < 4; ++mt) {
                float s1 = 0.f, s2 = 0.f;
                #pragma unroll
                for (int ntc = 0; ntc < 8; ++ntc) {
                    int n = wn + ntc * 8 + 2 * (lane & 3);
                    float c0 = cb[n], c1 = cb[n + 1];
                    float w0 = we_s[nb + n], w1 = we_s[nb + n + 1];
                    s1 += tanh_fast(acc[mt][ntc][0] + c0) * w0 + tanh_fast(acc[mt][ntc][1] + c1) * w1;
                    s2 += tanh_fast(acc[mt][ntc][2] + c0) * w0 + tanh_fast(acc[mt][ntc][3] + c1) * w1;
                    acc[mt][ntc][0] = 0.f; acc[mt][ntc][1] = 0.f;
                    acc[mt][ntc][2] = 0.f; acc[mt][ntc][3] = 0.f;
                }
                s1 += __shfl_xor_sync(0xffffffffu, s1, 1); s1 += __shfl_xor_sync(0xffffffffu, s1, 2);
                s2 += __shfl_xor_sync(0xffffffffu, s2, 1); s2 += __shfl_xor_sync(0xffffffffu, s2, 2);
                if ((lane & 3) == 0) {
                    int rl = wm + mt * 16 + (lane >> 2);
                    part[wx * 128 + rl]     = s1;
                    part[wx * 128 + rl + 8] = s2;
                }
            }
            __syncthreads();
            if (tid < 128)
                g_spart[(t & 1) * 65536 + m0 + tid] =
                    part[tid] + part[128 + tid] + part[256 + tid] + part[384 + tid];
        }
    }
}

// ---------------- fused softmax + context + cc (reads x_t fp16) ----------------
__global__ void softmax_ctx_cc(const float* __restrict__ emb,
                               const int* __restrict__ yPrev)
{
    int b = blockIdx.x, t = threadIdx.x;
    __shared__ float al[T_];
    __shared__ float red[T_];
    float v = g_spart[b * 256 + t] + g_spart[65536 + b * 256 + t];
    red[t] = v; __syncthreads();
    for (int s = 128; s; s >>= 1) { if (t < s) red[t] = fmaxf(red[t], red[t + s]); __syncthreads(); }
    float mx = red[0]; __syncthreads();
    float e = expf(v - mx);
    red[t] = e; __syncthreads();
    for (int s = 128; s; s >>= 1) { if (t < s) red[t] += red[t + s]; __syncthreads(); }
    al[t] = e / red[0];
    __syncthreads();

    float c0 = 0.f, c1 = 0.f;
    #pragma unroll 4
    for (int tt = 0; tt < 256; ++tt) {
        float a = al[tt];
        float2 xv = load_pair_tiled(g_x_t, 65536, b * 256 + tt, 2 * t);
        c0 += a * xv.x; c1 += a * xv.y;
    }
    store_pair_tiled(g_cc_t, 256, b, 512 + 2 * t, c0, c1);

    int y = yPrev[b];
    float2 ev = *(const float2*)(emb + (size_t)y * 512 + 2 * t);
    store_pair_tiled(g_cc_t, 256, b, 2 * t, ev.x, ev.y);
}

// ---------------- GRU elementwise ----------------
__global__ void gru_kernel(const float* __restrict__ s, float* __restrict__ h_out)
{
    int b = blockIdx.x, t = threadIdx.x;
    float hv[2];
    #pragma unroll
    for (int q = 0; q < 2; ++q) {
        int j = 2 * t + q;
        float ir = g_gi[b * 1536 + j];
        float iz = g_gi[b * 1536 + 512 + j];
        float in_ = g_gi[b * 1536 + 1024 + j];
        float hr = g_gh[b * 1536 + j];
        float hz = g_gh[b * 1536 + 512 + j];
        float hn = g_gh[b * 1536 + 1024 + j];
        float r = 1.f / (1.f + expf(-(ir + hr)));
        float z = 1.f / (1.f + expf(-(iz + hz)));
        float n = tanhf(in_ + r * hn);
        hv[q] = (1.f - z) * n + z * s[b * 512 + j];
        if (h_out) h_out[b * 512 + j] = hv[q];
    }
    store_pair_tiled(g_h_t, 256, b, 2 * t, hv[0], hv[1]);
}

// ======================================================================
extern "C" void kernel_launch(void* const* d_in, const int* in_sizes, int n_in,
                              void* d_out, int out_size)
{
    const float* x     = (const float*)d_in[0];
    const float* sPrev = (const float*)d_in[1];
    const int*   yPrev = (const int*)  d_in[2];
    const float* xe_w  = (const float*)d_in[3];
    const float* xe_b  = (const float*)d_in[4];
    const float* se_w  = (const float*)d_in[5];
    const float* se_b  = (const float*)d_in[6];
    const float* we_w  = (const float*)d_in[7];
    const float* emb   = (const float*)d_in[9];
    const float* w_ih  = (const float*)d_in[10];
    const float* w_hh  = (const float*)d_in[11];
    const float* b_ih  = (const float*)d_in[12];
    const float* b_hh  = (const float*)d_in[13];
    const float* fc_w  = (const float*)d_in[14];
    const float* fc_b  = (const float*)d_in[15];

    float* out = (float*)d_out;
    float* h_out = (out_size >= B_ * YD_ + B_ * 512) ? out + (size_t)B_ * YD_ : nullptr;

    float *sProj_p, *gi_p, *gh_p, *cbias_p;
    cudaGetSymbolAddress((void**)&sProj_p, g_sProj);
    cudaGetSymbolAddress((void**)&gi_p, g_gi);
    cudaGetSymbolAddress((void**)&gh_p, g_gh);
    cudaGetSymbolAddress((void**)&cbias_p, g_cbias);
    __half *s_t, *cc_t, *h_t, *se_t, *hh_t, *ih_t, *fc_t;
    cudaGetSymbolAddress((void**)&s_t,  g_s_t);
    cudaGetSymbolAddress((void**)&cc_t, g_cc_t);
    cudaGetSymbolAddress((void**)&h_t,  g_h_t);
    cudaGetSymbolAddress((void**)&se_t, g_se_t);
    cudaGetSymbolAddress((void**)&hh_t, g_hh_t);
    cudaGetSymbolAddress((void**)&ih_t, g_ih_t);
    cudaGetSymbolAddress((void**)&fc_t, g_fc_t);

    static cudaStream_t s2 = nullptr;
    static cudaEvent_t evFork = nullptr, evW = nullptr, evGH = nullptr;
    if (!s2) {
        cudaFuncSetAttribute(bulk_scores,      cudaFuncAttributeMaxDynamicSharedMemorySize, SMEM_S);
        cudaFuncSetAttribute(bulk_gemm<false>, cudaFuncAttributeMaxDynamicSharedMemorySize, SMEM_G);
        cudaFuncSetAttribute(bulk_gemm<true>,  cudaFuncAttributeMaxDynamicSharedMemorySize, SMEM_G);
        cudaStreamCreateWithFlags(&s2, cudaStreamNonBlocking);
        cudaEventCreateWithFlags(&evFork, cudaEventDisableTiming);
        cudaEventCreateWithFlags(&evW, cudaEventDisableTiming);
        cudaEventCreateWithFlags(&evGH, cudaEventDisableTiming);
    }

    // progress counters must be zero before split_x increments them
    zero_prog<<<2, 256>>>();

    // ---- capture fork ----
    cudaEventRecord(evFork, 0);
    cudaStreamWaitEvent(s2, evFork, 0);

    // ---- stream 2: x split (publishes g_xprog per 128-row block) ----
    split_x<<<16384, 256, 0, s2>>>(x);

    // ---- capture stream: s split, weight splits (+ cbias tail) ----
    split_gen<<<64, 256>>>(sPrev, s_t, 256, 512, 256 * 64);
    split_weights<<<(Q_TOT + 512 + 255) / 256, 256>>>(xe_w, se_w, w_hh, w_ih, fc_w, se_b, xe_b);
    cudaEventRecord(evW, 0);

    // gh on s2
    cudaStreamWaitEvent(s2, evW, 0);
    bulk_gemm<false><<<dim3(12, 4), 256, SMEM_G, s2>>>(s_t, 256, hh_t, 1536, b_hh, gh_p, 1536, 512);
    cudaEventRecord(evGH, s2);

    // ---- main chain (scores self-synchronizes against split_x via g_xprog) ----
    bulk_gemm<false><<<dim3(4, 4), 256, SMEM_G>>>(s_t, 256, se_t, 512, cbias_p, sProj_p, 512, 512);
    bulk_scores<<<GRID_S, 256, SMEM_S>>>(we_w);
    softmax_ctx_cc<<<256, 256>>>(emb, yPrev);
    bulk_gemm<false><<<dim3(12, 4), 256, SMEM_G>>>(cc_t, 256, ih_t, 1536, b_ih, gi_p, 1536, 1024);
    cudaStreamWaitEvent(0, evGH, 0);
    gru_kernel<<<256, 256>>>(sPrev, h_out);
    bulk_gemm<true><<<dim3(52, 4), 256, SMEM_G>>>(h_t, 256, fc_t, 6656, fc_b, out, 6625, 512);
}

// round 15
// speedup vs baseline: 1.9309x; 1.0391x over previous
#include <cuda_runtime.h>
#include <cuda_fp16.h>
#include <math.h>
#include <stdint.h>

#define B_  256
#define T_  256
#define YD_ 6625

// ---------------- fp32 scratch ----------------
__device__ float g_sProj[256 * 512];      // = s@se_w^T + (se_b + xe_b)
__device__ float g_spart[2 * 65536];
__device__ float g_gi[256 * 1536];
__device__ float g_gh[256 * 1536];
__device__ float g_cbias[512];
__device__ int   g_xprog[512];            // per-128-row-block x-split progress

// ---------------- chunk-tiled, pre-swizzled fp16 scratch ----------------
__device__ __half g_x_t [16u * 65536 * 32];
__device__ __half g_s_t [16 * 256 * 32];
__device__ __half g_cc_t[32 * 256 * 32];
__device__ __half g_h_t [16 * 256 * 32];
__device__ __half g_xe_t[16 * 512 * 32];
__device__ __half g_se_t[16 * 512 * 32];
__device__ __half g_hh_t[16 * 1536 * 32];
__device__ __half g_ih_t[32 * 1536 * 32];
__device__ __half g_fc_t[16 * 6656 * 32];

// ---------------- helpers ----------------
__device__ __forceinline__ uint32_t smem_u32(const void* p) {
    uint32_t a;
    asm("{ .reg .u64 t; cvta.to.shared.u64 t, %1; cvt.u32.u64 %0, t; }" : "=r"(a) : "l"(p));
    return a;
}
__device__ __forceinline__ void ldmx4(uint32_t addr, uint32_t* r) {
    asm volatile("ldmatrix.sync.aligned.m8n8.x4.shared.b16 {%0,%1,%2,%3}, [%4];"
        : "=r"(r[0]), "=r"(r[1]), "=r"(r[2]), "=r"(r[3]) : "r"(addr));
}
__device__ __forceinline__ void mma_f16(float* c, const uint32_t* a, uint32_t b0, uint32_t b1) {
    asm volatile("mma.sync.aligned.m16n8k16.row.col.f32.f16.f16.f32 "
        "{%0,%1,%2,%3}, {%4,%5,%6,%7}, {%8,%9}, {%0,%1,%2,%3};"
        : "+f"(c[0]), "+f"(c[1]), "+f"(c[2]), "+f"(c[3])
        : "r"(a[0]), "r"(a[1]), "r"(a[2]), "r"(a[3]), "r"(b0), "r"(b1));
}
#define MBAR_INIT(mb, c)  asm volatile("mbarrier.init.shared.b64 [%0], %1;" :: "r"(mb), "r"(c) : "memory")
#define MBAR_ARRIVE(mb)   asm volatile("mbarrier.arrive.shared.b64 _, [%0];" :: "r"(mb) : "memory")
#define MB_EXPECT(mb, n)  asm volatile("mbarrier.arrive.expect_tx.shared.b64 _, [%0], %1;" :: "r"(mb), "r"(n) : "memory")
#define FENCE_ASYNC()     asm volatile("fence.proxy.async.shared::cta;" ::: "memory")
#define BULK_G2S(dst, src, sz, mb) \
    asm volatile("cp.async.bulk.shared::cluster.global.mbarrier::complete_tx::bytes [%0], [%1], %2, [%3];" \
        :: "r"(dst), "l"(src), "r"(sz), "r"(mb) : "memory")

__device__ __forceinline__ void mbar_wait(uint32_t mb, uint32_t phase) {
    asm volatile(
        "{\n\t.reg .pred P;\n\t"
        "WL%=:\n\t"
        "mbarrier.try_wait.parity.acquire.cta.shared::cta.b64 P, [%0], %1, 0x989680;\n\t"
        "@!P bra WL%=;\n\t}"
        :: "r"(mb), "r"(phase) : "memory");
}

__device__ __forceinline__ float tanh_fast(float x) {
    float xc = fminf(fmaxf(x, -15.f), 15.f);
    float e = exp2f(xc * 2.8853900817779268f);
    return __fdividef(e - 1.0f, e + 1.0f);
}
__device__ __forceinline__ uint32_t pack_h2(float a, float b) {
    __half ha = __float2half_rn(a), hb = __float2half_rn(b);
    return (uint32_t)*(unsigned short*)&ha | ((uint32_t)*(unsigned short*)&hb << 16);
}

// ---------------- split writers ----------------
__device__ __forceinline__ void split_unit(const float* __restrict__ w,
                                           __half* __restrict__ out,
                                           int Rpad, int K, int u)
{
    int upr = K >> 3;
    int r = u / upr, uu = u - r * upr;
    int c = uu >> 2, j = uu & 3;
    const float4* src = (const float4*)(w + (size_t)r * K + c * 32 + j * 8);
    float4 v0 = src[0], v1 = src[1];
    float f[8] = {v0.x, v0.y, v0.z, v0.w, v1.x, v1.y, v1.z, v1.w};
    uint32_t h[4];
    #pragma unroll
    for (int i = 0; i < 4; i++) h[i] = pack_h2(f[2 * i], f[2 * i + 1]);
    size_t slab = ((size_t)c * Rpad + r) * 32;
    uint32_t sw = (uint32_t)(j ^ ((r >> 1) & 3)) << 4;
    *(uint4*)((char*)(out + slab) + sw) = make_uint4(h[0], h[1], h[2], h[3]);
}

__global__ void split_gen(const float* __restrict__ w, __half* __restrict__ out,
                          int Rpad, int K, int nunits)
{
    int u = blockIdx.x * blockDim.x + threadIdx.x;
    if (u < nunits) split_unit(w, out, Rpad, K, u);
}

__global__ void split_x(const float* __restrict__ x)
{
    int u = blockIdx.x * 256 + threadIdx.x;
    split_unit(x, g_x_t, 65536, 512, u);
    __syncthreads();
    if (threadIdx.x == 0) {
        __threadfence();
        atomicAdd(&g_xprog[blockIdx.x >> 5], 1);
    }
}

__global__ void zero_prog()
{
    int i = blockIdx.x * 256 + threadIdx.x;
    if (i < 512) g_xprog[i] = 0;
}

#define Q_TOT 784448
__global__ void split_weights(const float* xe, const float* se, const float* hh,
                              const float* ih, const float* fc,
                              const float* se_b, const float* xe_b)
{
    int u = blockIdx.x * blockDim.x + threadIdx.x;
    if (u < 32768)  { split_unit(xe, g_xe_t, 512, 512, u); return; }  u -= 32768;
    if (u < 32768)  { split_unit(se, g_se_t, 512, 512, u); return; }  u -= 32768;
    if (u < 98304)  { split_unit(hh, g_hh_t, 1536, 512, u); return; } u -= 98304;
    if (u < 196608) { split_unit(ih, g_ih_t, 1536, 1024, u); return; } u -= 196608;
    if (u < 424000) { split_unit(fc, g_fc_t, 6656, 512, u); return; } u -= 424000;
    if (u < 512)    { g_cbias[u] = se_b[u] + xe_b[u]; }
}

__device__ __forceinline__ void store_pair_tiled(__half* base, int Rpad,
                                                 int r, int col, float v0, float v1)
{
    uint32_t hi = pack_h2(v0, v1);
    int c = col >> 5, k = col & 31, j = k >> 3;
    size_t slab = ((size_t)c * Rpad + r) * 32;
    uint32_t sw = ((uint32_t)(j ^ ((r >> 1) & 3)) << 4) + (k & 7) * 2;
    *(uint32_t*)((char*)(base + slab) + sw) = hi;
}
__device__ __forceinline__ float2 load_pair_tiled(const __half* base, int Rpad,
                                                  int r, int col)
{
    int c = col >> 5, k = col & 31, j = k >> 3;
    size_t slab = ((size_t)c * Rpad + r) * 32;
    uint32_t sw = ((uint32_t)(j ^ ((r >> 1) & 3)) << 4) + (k & 7) * 2;
    __half2 v = *(const __half2*)((const char*)(base + slab) + sw);
    return __half22float2(v);
}

// ============ small GEMM: M-tile 64, N-tile 128, 3 stages, 256 thr ============
#define STG_G   12288
#define MB_G    (3 * STG_G)
#define SMEM_G  (MB_G + 64)

__device__ __forceinline__ void issue64(uint32_t stbase, uint32_t mb,
        const __half* At, int RpadA, int m0,
        const __half* Wt, int RpadW, int nb, int chunk)
{
    MB_EXPECT(mb, 12288u);
    const char* a0 = (const char*)(At + ((size_t)chunk * RpadA + m0) * 32);
    const char* w0 = (const char*)(Wt + ((size_t)chunk * RpadW + nb) * 32);
    BULK_G2S(stbase,         a0, 4096u, mb);
    BULK_G2S(stbase + 4096,  w0, 8192u, mb);
}

__device__ __forceinline__ void cchunk64(uint32_t aB, uint32_t wB, int lane,
                                         int wm, int wn, float (&acc)[2][4][4])
{
    #pragma unroll
    for (int ks = 0; ks < 2; ++ks) {
        uint32_t Ah[2][4];
        #pragma unroll
        for (int mt = 0; mt < 2; ++mt) {
            int row = wm + mt * 16 + (lane & 15);
            uint32_t col = (uint32_t)((ks * 2 + (lane >> 4)) ^ ((row >> 1) & 3));
            ldmx4(aB + (uint32_t)row * 64 + col * 16, Ah[mt]);
        }
        #pragma unroll
        for (int g = 0; g < 2; ++g) {
            int row = wn + g * 16 + ((lane >> 4) << 3) + (lane & 7);
            uint32_t col = (uint32_t)((ks * 2 + ((lane >> 3) & 1)) ^ ((row >> 1) & 3));
            uint32_t bh[4];
            ldmx4(wB + (uint32_t)row * 64 + col * 16, bh);
            #pragma unroll
            for (int mt = 0; mt < 2; ++mt)
                #pragma unroll
                for (int h = 0; h < 2; ++h)
                    mma_f16(acc[mt][g * 2 + h], Ah[mt], bh[2 * h], bh[2 * h + 1]);
        }
    }
}

template<bool GUARD>
__global__ void __launch_bounds__(256, 1)
bulk_gemm(const __half* __restrict__ At, int RpadA,
          const __half* __restrict__ Wt, int RpadW,
          const float* __restrict__ bias, float* __restrict__ C, int N, int K)
{
    extern __shared__ char smc[];
    uint32_t sm = smem_u32(smc);
    int tid = threadIdx.x, lane = tid & 31, wid = tid >> 5;
    int wm = (wid >> 2) * 32, wn = (wid & 3) * 32;
    int m0 = blockIdx.y * 64, nb = blockIdx.x * 128;
    uint32_t mb = sm + MB_G;
    int NC = K >> 5;

    if (tid == 0) {
        for (int s = 0; s < 3; s++) MBAR_INIT(mb + 8 * s, 1);
    }
    __syncthreads();
    if (tid == 0) {
        FENCE_ASYNC();
        for (int s = 0; s < 3; s++)
            issue64(sm + s * STG_G, mb + 8 * s, At, RpadA, m0, Wt, RpadW, nb, s);
    }

    float acc[2][4][4] = {};
    for (int c = 0; c < NC; ++c) {
        int st = c % 3;
        mbar_wait(mb + 8 * st, (uint32_t)((c / 3) & 1));
        cchunk64(sm + st * STG_G, sm + st * STG_G + 4096, lane, wm, wn, acc);
        __syncthreads();
        if (tid == 0 && c + 3 < NC) {
            FENCE_ASYNC();
            issue64(sm + st * STG_G, mb + 8 * st, At, RpadA, m0, Wt, RpadW, nb, c + 3);
        }
    }

    #pragma unroll
    for (int mt = 0; mt < 2; ++mt) {
        int r1 = m0 + wm + mt * 16 + (lane >> 2), r2 = r1 + 8;
        #pragma unroll
        for (int nt = 0; nt < 4; ++nt) {
            int n = nb + wn + nt * 8 + 2 * (lane & 3);
            if (!GUARD || n < N) {
                float b0 = bias[n];
                C[(size_t)r1 * N + n] = acc[mt][nt][0] + b0;
                C[(size_t)r2 * N + n] = acc[mt][nt][2] + b0;
                if (!GUARD || n + 1 < N) {
                    float b1 = bias[n + 1];
                    C[(size_t)r1 * N + n + 1] = acc[mt][nt][1] + b1;
                    C[(size_t)r2 * N + n + 1] = acc[mt][nt][3] + b1;
                }
            }
        }
    }
}

// ============ persistent scores kernel: grid 148, 256 thr, tile 128x256 ============
#define STG_S   24576            // A 8K | W 16K
#define TAB_S   (3 * STG_S)
#define MB_S    (TAB_S + 6144)   // full mbars at +0, empty mbars at +24
#define SMEM_S  (MB_S + 64)
#define NTILES  1024
#define GRID_S  148

__device__ __forceinline__ void issue128(uint32_t stbase, uint32_t mb, int m0, int nb, int chunk)
{
    MB_EXPECT(mb, 24576u);
    const char* a0 = (const char*)(g_x_t + ((size_t)chunk * 65536 + m0) * 32);
    const char* w0 = (const char*)(g_xe_t + ((size_t)chunk * 512 + nb) * 32);
    BULK_G2S(stbase,         a0, 8192u,  mb);
    BULK_G2S(stbase + 8192,  w0, 16384u, mb);
}

__device__ __forceinline__ void cchunk128(uint32_t aB, uint32_t wB, int lane,
                                          int wm, int wn, float (&acc)[4][8][4])
{
    #pragma unroll
    for (int ks = 0; ks < 2; ++ks) {
        uint32_t Ah[4][4];
        #pragma unroll
        for (int mt = 0; mt < 4; ++mt) {
            int row = wm + mt * 16 + (lane & 15);
            uint32_t col = (uint32_t)((ks * 2 + (lane >> 4)) ^ ((row >> 1) & 3));
            ldmx4(aB + (uint32_t)row * 64 + col * 16, Ah[mt]);
        }
        #pragma unroll
        for (int g = 0; g < 4; ++g) {
            int row = wn + g * 16 + ((lane >> 4) << 3) + (lane & 7);
            uint32_t col = (uint32_t)((ks * 2 + ((lane >> 3) & 1)) ^ ((row >> 1) & 3));
            uint32_t bh[4];
            ldmx4(wB + (uint32_t)row * 64 + col * 16, bh);
            #pragma unroll
            for (int mt = 0; mt < 4; ++mt)
                #pragma unroll
                for (int h = 0; h < 2; ++h)
                    mma_f16(acc[mt][g * 2 + h], Ah[mt], bh[2 * h], bh[2 * h + 1]);
        }
    }
}

__device__ __forceinline__ void issue_tile(uint32_t sm, uint32_t mb, int bid, int gq)
{
    int t = bid + (gq >> 4) * GRID_S;
    int chunk = gq & 15;
    if (chunk == 0) {
        volatile int* p = &g_xprog[t >> 1];
        while (*p < 32) { }
    }
    int m0 = (t >> 1) << 7;
    int nb = (t & 1) << 8;
    int st = gq % 3;
    issue128(sm + st * STG_S, mb + 8 * st, m0, nb, chunk);
}

__global__ void __launch_bounds__(256, 1)
bulk_scores(const float* __restrict__ we)
{
    extern __shared__ char smc[];
    uint32_t sm = smem_u32(smc);
    int tid = threadIdx.x, lane = tid & 31, wid = tid >> 5;
    int wm = (wid >> 2) * 64, wn = (wid & 3) * 64;
    int wx = wid & 3;
    int bid = blockIdx.x;
    uint32_t mb  = sm + MB_S;        // 3 full mbars
    uint32_t mbe = sm + MB_S + 24;   // 3 empty mbars (count 8)

    float* we_s  = (float*)(smc + TAB_S);
    float* cbbuf = we_s + 512;
    float* part  = cbbuf + 512;

    we_s[tid]       = we[tid];
    we_s[tid + 256] = we[tid + 256];

    int nt_cta = (NTILES - bid + GRID_S - 1) / GRID_S;
    int total = nt_cta * 16;

    if (tid == 0) {
        for (int s = 0; s < 3; s++) { MBAR_INIT(mb + 8 * s, 1); MBAR_INIT(mbe + 8 * s, 8); }
    }
    __syncthreads();
    if (tid == 0) {
        FENCE_ASYNC();
        for (int s = 0; s < 3; s++) issue_tile(sm, mb, bid, s);
    }

    float acc[4][8][4] = {};
    for (int gq = 0; gq < total; ++gq) {
        int tt = gq >> 4;
        int t  = bid + tt * GRID_S;
        int st = gq % 3;
        if ((gq & 15) == 0) {
            int bidx = t >> 2;
            int nb   = (t & 1) << 8;
            cbbuf[(tt & 1) * 256 + tid] = g_sProj[bidx * 512 + nb + tid];
        }
        mbar_wait(mb + 8 * st, (uint32_t)((gq / 3) & 1));
        cchunk128(sm + st * STG_S, sm + st * STG_S + 8192, lane, wm, wn, acc);
        if (lane == 0) MBAR_ARRIVE(mbe + 8 * st);
        if (tid == 0 && gq + 3 < total) {
            mbar_wait(mbe + 8 * st, (uint32_t)((gq / 3) & 1));
            FENCE_ASYNC();
            issue_tile(sm, mb, bid, gq + 3);
        }
        if ((gq & 15) == 15) {
            __syncthreads();
            int m0 = (t >> 1) << 7;
            int nb = (t & 1) << 8;
            float* cb = cbbuf + (tt & 1) * 256;
            #pragma unroll
            for (int mt = 0; mt < 4; ++mt) {
                float s1 = 0.f, s2 = 0.f;
                #pragma unroll
                for (int ntc = 0; ntc < 8; ++ntc) {
                    int n = wn + ntc * 8 + 2 * (lane & 3);
                    float c0 = cb[n], c1 = cb[n + 1];
                    float w0 = we_s[nb + n], w1 = we_s[nb + n + 1];
                    s1 += tanh_fast(acc[mt][ntc][0] + c0) * w0 + tanh_fast(acc[mt][ntc][1] + c1) * w1;
                    s2 += tanh_fast(acc[mt][ntc][2] + c0) * w0 + tanh_fast(acc[mt][ntc][3] + c1) * w1;
                    acc[mt][ntc][0] = 0.f; acc[mt][ntc][1] = 0.f;
                    acc[mt][ntc][2] = 0.f; acc[mt][ntc][3] = 0.f;
                }
                s1 += __shfl_xor_sync(0xffffffffu, s1, 1); s1 += __shfl_xor_sync(0xffffffffu, s1, 2);
                s2 += __shfl_xor_sync(0xffffffffu, s2, 1); s2 += __shfl_xor_sync(0xffffffffu, s2, 2);
                if ((lane & 3) == 0) {
                    int rl = wm + mt * 16 + (lane >> 2);
                    part[wx * 128 + rl]     = s1;
                    part[wx * 128 + rl + 8] = s2;
                }
            }
            __syncthreads();
            if (tid < 128)
                g_spart[(t & 1) * 65536 + m0 + tid] =
                    part[tid] + part[128 + tid] + part[256 + tid] + part[384 + tid];
            __syncthreads();
        }
    }
}

// ---------------- fused softmax + context + cc (stream-ordered after scores) ----
__global__ void softmax_ctx_cc(const float* __restrict__ emb,
                               const int* __restrict__ yPrev)
{
    int b = blockIdx.x, t = threadIdx.x;
    __shared__ float al[T_];
    __shared__ float red[T_];
    float v = g_spart[b * 256 + t] + g_spart[65536 + b * 256 + t];
    red[t] = v; __syncthreads();
    for (int s = 128; s; s >>= 1) { if (t < s) red[t] = fmaxf(red[t], red[t + s]); __syncthreads(); }
    float mx = red[0]; __syncthreads();
    float e = expf(v - mx);
    red[t] = e; __syncthreads();
    for (int s = 128; s; s >>= 1) { if (t < s) red[t] += red[t + s]; __syncthreads(); }
    al[t] = e / red[0];
    __syncthreads();

    float c0 = 0.f, c1 = 0.f;
    #pragma unroll 4
    for (int tt = 0; tt < 256; ++tt) {
        float a = al[tt];
        float2 xv = load_pair_tiled(g_x_t, 65536, b * 256 + tt, 2 * t);
        c0 += a * xv.x; c1 += a * xv.y;
    }
    store_pair_tiled(g_cc_t, 256, b, 512 + 2 * t, c0, c1);

    int y = yPrev[b];
    float2 ev = *(const float2*)(emb + (size_t)y * 512 + 2 * t);
    store_pair_tiled(g_cc_t, 256, b, 2 * t, ev.x, ev.y);
}

// ---------------- GRU elementwise ----------------
__global__ void gru_kernel(const float* __restrict__ s, float* __restrict__ h_out)
{
    int b = blockIdx.x, t = threadIdx.x;
    float hv[2];
    #pragma unroll
    for (int q = 0; q < 2; ++q) {
        int j = 2 * t + q;
        float ir = g_gi[b * 1536 + j];
        float iz = g_gi[b * 1536 + 512 + j];
        float in_ = g_gi[b * 1536 + 1024 + j];
        float hr = g_gh[b * 1536 + j];
        float hz = g_gh[b * 1536 + 512 + j];
        float hn = g_gh[b * 1536 + 1024 + j];
        float r = 1.f / (1.f + expf(-(ir + hr)));
        float z = 1.f / (1.f + expf(-(iz + hz)));
        float n = tanhf(in_ + r * hn);
        hv[q] = (1.f - z) * n + z * s[b * 512 + j];
        if (h_out) h_out[b * 512 + j] = hv[q];
    }
    store_pair_tiled(g_h_t, 256, b, 2 * t, hv[0], hv[1]);
}

// ======================================================================
extern "C" void kernel_launch(void* const* d_in, const int* in_sizes, int n_in,
                              void* d_out, int out_size)
{
    const float* x     = (const float*)d_in[0];
    const float* sPrev = (const float*)d_in[1];
    const int*   yPrev = (const int*)  d_in[2];
    const float* xe_w  = (const float*)d_in[3];
    const float* xe_b  = (const float*)d_in[4];
    const float* se_w  = (const float*)d_in[5];
    const float* se_b  = (const float*)d_in[6];
    const float* we_w  = (const float*)d_in[7];
    const float* emb   = (const float*)d_in[9];
    const float* w_ih  = (const float*)d_in[10];
    const float* w_hh  = (const float*)d_in[11];
    const float* b_ih  = (const float*)d_in[12];
    const float* b_hh  = (const float*)d_in[13];
    const float* fc_w  = (const float*)d_in[14];
    const float* fc_b  = (const float*)d_in[15];

    float* out = (float*)d_out;
    float* h_out = (out_size >= B_ * YD_ + B_ * 512) ? out + (size_t)B_ * YD_ : nullptr;

    float *sProj_p, *gi_p, *gh_p, *cbias_p;
    cudaGetSymbolAddress((void**)&sProj_p, g_sProj);
    cudaGetSymbolAddress((void**)&gi_p, g_gi);
    cudaGetSymbolAddress((void**)&gh_p, g_gh);
    cudaGetSymbolAddress((void**)&cbias_p, g_cbias);
    __half *s_t, *cc_t, *h_t, *se_t, *hh_t, *ih_t, *fc_t;
    cudaGetSymbolAddress((void**)&s_t,  g_s_t);
    cudaGetSymbolAddress((void**)&cc_t, g_cc_t);
    cudaGetSymbolAddress((void**)&h_t,  g_h_t);
    cudaGetSymbolAddress((void**)&se_t, g_se_t);
    cudaGetSymbolAddress((void**)&hh_t, g_hh_t);
    cudaGetSymbolAddress((void**)&ih_t, g_ih_t);
    cudaGetSymbolAddress((void**)&fc_t, g_fc_t);

    static cudaStream_t s2 = nullptr;
    static cudaEvent_t evFork = nullptr, evW = nullptr, evGH = nullptr;
    if (!s2) {
        cudaFuncSetAttribute(bulk_scores,      cudaFuncAttributeMaxDynamicSharedMemorySize, SMEM_S);
        cudaFuncSetAttribute(bulk_gemm<false>, cudaFuncAttributeMaxDynamicSharedMemorySize, SMEM_G);
        cudaFuncSetAttribute(bulk_gemm<true>,  cudaFuncAttributeMaxDynamicSharedMemorySize, SMEM_G);
        cudaStreamCreateWithFlags(&s2, cudaStreamNonBlocking);
        cudaEventCreateWithFlags(&evFork, cudaEventDisableTiming);
        cudaEventCreateWithFlags(&evW, cudaEventDisableTiming);
        cudaEventCreateWithFlags(&evGH, cudaEventDisableTiming);
    }

    // progress counters must be zero before split_x increments them
    zero_prog<<<2, 256>>>();

    // ---- capture fork ----
    cudaEventRecord(evFork, 0);
    cudaStreamWaitEvent(s2, evFork, 0);

    // ---- stream 2: x split (publishes g_xprog) ----
    split_x<<<16384, 256, 0, s2>>>(x);

    // ---- capture stream: s split, weight splits (+ cbias tail) ----
    split_gen<<<64, 256>>>(sPrev, s_t, 256, 512, 256 * 64);
    split_weights<<<(Q_TOT + 512 + 255) / 256, 256>>>(xe_w, se_w, w_hh, w_ih, fc_w, se_b, xe_b);
    cudaEventRecord(evW, 0);

    // gh on s2
    cudaStreamWaitEvent(s2, evW, 0);
    bulk_gemm<false><<<dim3(12, 4), 256, SMEM_G, s2>>>(s_t, 256, hh_t, 1536, b_hh, gh_p, 1536, 512);
    cudaEventRecord(evGH, s2);

    // ---- main chain (scores self-synchronizes against split_x via g_xprog) ----
    bulk_gemm<false><<<dim3(4, 4), 256, SMEM_G>>>(s_t, 256, se_t, 512, cbias_p, sProj_p, 512, 512);
    bulk_scores<<<GRID_S, 256, SMEM_S>>>(we_w);
    softmax_ctx_cc<<<256, 256>>>(emb, yPrev);
    bulk_gemm<false><<<dim3(12, 4), 256, SMEM_G>>>(cc_t, 256, ih_t, 1536, b_ih, gi_p, 1536, 1024);
    cudaStreamWaitEvent(0, evGH, 0);
    gru_kernel<<<256, 256>>>(sPrev, h_out);
    bulk_gemm<true><<<dim3(52, 4), 256, SMEM_G>>>(h_t, 256, fc_t, 6656, fc_b, out, 6625, 512);
}

// round 16
// speedup vs baseline: 2.0027x; 1.0372x over previous
#include <cuda_runtime.h>
#include <cuda_fp16.h>
#include <math.h>
#include <stdint.h>

#define B_  256
#define T_  256
#define YD_ 6625

// ---------------- fp32 scratch ----------------
__device__ float g_sProj[256 * 512];      // = s@se_w^T + (se_b + xe_b)
__device__ float g_spart[2 * 65536];
__device__ float g_gi[256 * 1536];
__device__ float g_gh[256 * 1536];
__device__ float g_cbias[512];
__device__ int   g_xprog[512];            // per-128-row-block x-split progress

// ---------------- chunk-tiled, pre-swizzled fp16 scratch ----------------
__device__ __half g_x_t [16u * 65536 * 32];
__device__ __half g_s_t [16 * 256 * 32];
__device__ __half g_cc_t[32 * 256 * 32];
__device__ __half g_h_t [16 * 256 * 32];
__device__ __half g_xe_t[16 * 512 * 32];
__device__ __half g_se_t[16 * 512 * 32];
__device__ __half g_hh_t[16 * 1536 * 32];
__device__ __half g_ih_t[32 * 1536 * 32];
__device__ __half g_fc_t[16 * 6656 * 32];

// ---------------- helpers ----------------
__device__ __forceinline__ uint32_t smem_u32(const void* p) {
    uint32_t a;
    asm("{ .reg .u64 t; cvta.to.shared.u64 t, %1; cvt.u32.u64 %0, t; }" : "=r"(a) : "l"(p));
    return a;
}
__device__ __forceinline__ void ldmx4(uint32_t addr, uint32_t* r) {
    asm volatile("ldmatrix.sync.aligned.m8n8.x4.shared.b16 {%0,%1,%2,%3}, [%4];"
        : "=r"(r[0]), "=r"(r[1]), "=r"(r[2]), "=r"(r[3]) : "r"(addr));
}
__device__ __forceinline__ void mma_f16(float* c, const uint32_t* a, uint32_t b0, uint32_t b1) {
    asm volatile("mma.sync.aligned.m16n8k16.row.col.f32.f16.f16.f32 "
        "{%0,%1,%2,%3}, {%4,%5,%6,%7}, {%8,%9}, {%0,%1,%2,%3};"
        : "+f"(c[0]), "+f"(c[1]), "+f"(c[2]), "+f"(c[3])
        : "r"(a[0]), "r"(a[1]), "r"(a[2]), "r"(a[3]), "r"(b0), "r"(b1));
}
#define MBAR_INIT(mb, c)  asm volatile("mbarrier.init.shared.b64 [%0], %1;" :: "r"(mb), "r"(c) : "memory")
#define MBAR_ARRIVE(mb)   asm volatile("mbarrier.arrive.shared.b64 _, [%0];" :: "r"(mb) : "memory")
#define MB_EXPECT(mb, n)  asm volatile("mbarrier.arrive.expect_tx.shared.b64 _, [%0], %1;" :: "r"(mb), "r"(n) : "memory")
#define FENCE_ASYNC()     asm volatile("fence.proxy.async.shared::cta;" ::: "memory")
#define BULK_G2S(dst, src, sz, mb) \
    asm volatile("cp.async.bulk.shared::cluster.global.mbarrier::complete_tx::bytes [%0], [%1], %2, [%3];" \
        :: "r"(dst), "l"(src), "r"(sz), "r"(mb) : "memory")

__device__ __forceinline__ void mbar_wait(uint32_t mb, uint32_t phase) {
    asm volatile(
        "{\n\t.reg .pred P;\n\t"
        "WL%=:\n\t"
        "mbarrier.try_wait.parity.acquire.cta.shared::cta.b64 P, [%0], %1, 0x989680;\n\t"
        "@!P bra WL%=;\n\t}"
        :: "r"(mb), "r"(phase) : "memory");
}

__device__ __forceinline__ float tanh_fast(float x) {
    float xc = fminf(fmaxf(x, -15.f), 15.f);
    float e = exp2f(xc * 2.8853900817779268f);
    return __fdividef(e - 1.0f, e + 1.0f);
}
__device__ __forceinline__ uint32_t pack_h2(float a, float b) {
    __half ha = __float2half_rn(a), hb = __float2half_rn(b);
    return (uint32_t)*(unsigned short*)&ha | ((uint32_t)*(unsigned short*)&hb << 16);
}

// ---------------- split writers ----------------
__device__ __forceinline__ void split_unit(const float* __restrict__ w,
                                           __half* __restrict__ out,
                                           int Rpad, int K, int u)
{
    int upr = K >> 3;
    int r = u / upr, uu = u - r * upr;
    int c = uu >> 2, j = uu & 3;
    const float4* src = (const float4*)(w + (size_t)r * K + c * 32 + j * 8);
    float4 v0 = src[0], v1 = src[1];
    float f[8] = {v0.x, v0.y, v0.z, v0.w, v1.x, v1.y, v1.z, v1.w};
    uint32_t h[4];
    #pragma unroll
    for (int i = 0; i < 4; i++) h[i] = pack_h2(f[2 * i], f[2 * i + 1]);
    size_t slab = ((size_t)c * Rpad + r) * 32;
    uint32_t sw = (uint32_t)(j ^ ((r >> 1) & 3)) << 4;
    *(uint4*)((char*)(out + slab) + sw) = make_uint4(h[0], h[1], h[2], h[3]);
}

__global__ void split_gen(const float* __restrict__ w, __half* __restrict__ out,
                          int Rpad, int K, int nunits)
{
    int u = blockIdx.x * blockDim.x + threadIdx.x;
    if (u < nunits) split_unit(w, out, Rpad, K, u);
}

__global__ void split_x(const float* __restrict__ x)
{
    int u = blockIdx.x * 256 + threadIdx.x;
    split_unit(x, g_x_t, 65536, 512, u);
    __syncthreads();
    if (threadIdx.x == 0) {
        __threadfence();
        atomicAdd(&g_xprog[blockIdx.x >> 5], 1);
    }
}

__global__ void zero_prog()
{
    int i = blockIdx.x * 256 + threadIdx.x;
    if (i < 512) g_xprog[i] = 0;
}

#define Q_TOT 784448
__global__ void split_weights(const float* xe, const float* se, const float* hh,
                              const float* ih, const float* fc,
                              const float* se_b, const float* xe_b)
{
    int u = blockIdx.x * blockDim.x + threadIdx.x;
    if (u < 32768)  { split_unit(xe, g_xe_t, 512, 512, u); return; }  u -= 32768;
    if (u < 32768)  { split_unit(se, g_se_t, 512, 512, u); return; }  u -= 32768;
    if (u < 98304)  { split_unit(hh, g_hh_t, 1536, 512, u); return; } u -= 98304;
    if (u < 196608) { split_unit(ih, g_ih_t, 1536, 1024, u); return; } u -= 196608;
    if (u < 424000) { split_unit(fc, g_fc_t, 6656, 512, u); return; } u -= 424000;
    if (u < 512)    { g_cbias[u] = se_b[u] + xe_b[u]; }
}

__device__ __forceinline__ void store_pair_tiled(__half* base, int Rpad,
                                                 int r, int col, float v0, float v1)
{
    uint32_t hi = pack_h2(v0, v1);
    int c = col >> 5, k = col & 31, j = k >> 3;
    size_t slab = ((size_t)c * Rpad + r) * 32;
    uint32_t sw = ((uint32_t)(j ^ ((r >> 1) & 3)) << 4) + (k & 7) * 2;
    *(uint32_t*)((char*)(base + slab) + sw) = hi;
}
__device__ __forceinline__ float2 load_pair_tiled(const __half* base, int Rpad,
                                                  int r, int col)
{
    int c = col >> 5, k = col & 31, j = k >> 3;
    size_t slab = ((size_t)c * Rpad + r) * 32;
    uint32_t sw = ((uint32_t)(j ^ ((r >> 1) & 3)) << 4) + (k & 7) * 2;
    __half2 v = *(const __half2*)((const char*)(base + slab) + sw);
    return __half22float2(v);
}

// ============ small GEMM: M-tile 64, N-tile 128, 3 stages, 256 thr ============
#define STG_G   12288
#define MB_G    (3 * STG_G)
#define SMEM_G  (MB_G + 64)

__device__ __forceinline__ void issue64(uint32_t stbase, uint32_t mb,
        const __half* At, int RpadA, int m0,
        const __half* Wt, int RpadW, int nb, int chunk)
{
    MB_EXPECT(mb, 12288u);
    const char* a0 = (const char*)(At + ((size_t)chunk * RpadA + m0) * 32);
    const char* w0 = (const char*)(Wt + ((size_t)chunk * RpadW + nb) * 32);
    BULK_G2S(stbase,         a0, 4096u, mb);
    BULK_G2S(stbase + 4096,  w0, 8192u, mb);
}

__device__ __forceinline__ void cchunk64(uint32_t aB, uint32_t wB, int lane,
                                         int wm, int wn, float (&acc)[2][4][4])
{
    #pragma unroll
    for (int ks = 0; ks < 2; ++ks) {
        uint32_t Ah[2][4];
        #pragma unroll
        for (int mt = 0; mt < 2; ++mt) {
            int row = wm + mt * 16 + (lane & 15);
            uint32_t col = (uint32_t)((ks * 2 + (lane >> 4)) ^ ((row >> 1) & 3));
            ldmx4(aB + (uint32_t)row * 64 + col * 16, Ah[mt]);
        }
        #pragma unroll
        for (int g = 0; g < 2; ++g) {
            int row = wn + g * 16 + ((lane >> 4) << 3) + (lane & 7);
            uint32_t col = (uint32_t)((ks * 2 + ((lane >> 3) & 1)) ^ ((row >> 1) & 3));
            uint32_t bh[4];
            ldmx4(wB + (uint32_t)row * 64 + col * 16, bh);
            #pragma unroll
            for (int mt = 0; mt < 2; ++mt)
                #pragma unroll
                for (int h = 0; h < 2; ++h)
                    mma_f16(acc[mt][g * 2 + h], Ah[mt], bh[2 * h], bh[2 * h + 1]);
        }
    }
}

template<bool GUARD>
__global__ void __launch_bounds__(256, 1)
bulk_gemm(const __half* __restrict__ At, int RpadA,
          const __half* __restrict__ Wt, int RpadW,
          const float* __restrict__ bias, float* __restrict__ C, int N, int K)
{
    extern __shared__ char smc[];
    uint32_t sm = smem_u32(smc);
    int tid = threadIdx.x, lane = tid & 31, wid = tid >> 5;
    int wm = (wid >> 2) * 32, wn = (wid & 3) * 32;
    int m0 = blockIdx.y * 64, nb = blockIdx.x * 128;
    uint32_t mb = sm + MB_G;
    int NC = K >> 5;

    if (tid == 0) {
        for (int s = 0; s < 3; s++) MBAR_INIT(mb + 8 * s, 1);
    }
    __syncthreads();
    if (tid == 0) {
        FENCE_ASYNC();
        for (int s = 0; s < 3; s++)
            issue64(sm + s * STG_G, mb + 8 * s, At, RpadA, m0, Wt, RpadW, nb, s);
    }

    float acc[2][4][4] = {};
    for (int c = 0; c < NC; ++c) {
        int st = c % 3;
        mbar_wait(mb + 8 * st, (uint32_t)((c / 3) & 1));
        cchunk64(sm + st * STG_G, sm + st * STG_G + 4096, lane, wm, wn, acc);
        __syncthreads();
        if (tid == 0 && c + 3 < NC) {
            FENCE_ASYNC();
            issue64(sm + st * STG_G, mb + 8 * st, At, RpadA, m0, Wt, RpadW, nb, c + 3);
        }
    }

    #pragma unroll
    for (int mt = 0; mt < 2; ++mt) {
        int r1 = m0 + wm + mt * 16 + (lane >> 2), r2 = r1 + 8;
        #pragma unroll
        for (int nt = 0; nt < 4; ++nt) {
            int n = nb + wn + nt * 8 + 2 * (lane & 3);
            if (!GUARD || n < N) {
                float b0 = bias[n];
                C[(size_t)r1 * N + n] = acc[mt][nt][0] + b0;
                C[(size_t)r2 * N + n] = acc[mt][nt][2] + b0;
                if (!GUARD || n + 1 < N) {
                    float b1 = bias[n + 1];
                    C[(size_t)r1 * N + n + 1] = acc[mt][nt][1] + b1;
                    C[(size_t)r2 * N + n + 1] = acc[mt][nt][3] + b1;
                }
            }
        }
    }
}

// ============ persistent scores kernel: grid 148, 256 thr, tile 128x256,
//              K-chunk 64, 4 stages ============
#define STG_S   49152            // A0 8K | A1 8K | W0 16K | W1 16K
#define NSTG_S  4
#define TAB_S   (NSTG_S * STG_S) // 196608
#define MB_S    (TAB_S + 6144)
#define SMEM_S  (MB_S + 80)
#define NTILES  1024
#define GRID_S  148

__device__ __forceinline__ void issue128(uint32_t stbase, uint32_t mb, int m0, int nb, int chunk)
{
    MB_EXPECT(mb, 49152u);
    const char* a0 = (const char*)(g_x_t + ((size_t)(chunk * 2 + 0) * 65536 + m0) * 32);
    const char* a1 = (const char*)(g_x_t + ((size_t)(chunk * 2 + 1) * 65536 + m0) * 32);
    const char* w0 = (const char*)(g_xe_t + ((size_t)(chunk * 2 + 0) * 512 + nb) * 32);
    const char* w1 = (const char*)(g_xe_t + ((size_t)(chunk * 2 + 1) * 512 + nb) * 32);
    BULK_G2S(stbase,          a0, 8192u,  mb);
    BULK_G2S(stbase + 8192,   a1, 8192u,  mb);
    BULK_G2S(stbase + 16384,  w0, 16384u, mb);
    BULK_G2S(stbase + 32768,  w1, 16384u, mb);
}

__device__ __forceinline__ void cchunk128(uint32_t stg, int lane,
                                          int wm, int wn, float (&acc)[4][8][4])
{
    #pragma unroll
    for (int sl = 0; sl < 2; ++sl) {
        uint32_t aB = stg + sl * 8192;
        uint32_t wB = stg + 16384 + sl * 16384;
        #pragma unroll
        for (int ks = 0; ks < 2; ++ks) {
            uint32_t Ah[4][4];
            #pragma unroll
            for (int mt = 0; mt < 4; ++mt) {
                int row = wm + mt * 16 + (lane & 15);
                uint32_t col = (uint32_t)((ks * 2 + (lane >> 4)) ^ ((row >> 1) & 3));
                ldmx4(aB + (uint32_t)row * 64 + col * 16, Ah[mt]);
            }
            #pragma unroll
            for (int g = 0; g < 4; ++g) {
                int row = wn + g * 16 + ((lane >> 4) << 3) + (lane & 7);
                uint32_t col = (uint32_t)((ks * 2 + ((lane >> 3) & 1)) ^ ((row >> 1) & 3));
                uint32_t bh[4];
                ldmx4(wB + (uint32_t)row * 64 + col * 16, bh);
                #pragma unroll
                for (int mt = 0; mt < 4; ++mt)
                    #pragma unroll
                    for (int h = 0; h < 2; ++h)
                        mma_f16(acc[mt][g * 2 + h], Ah[mt], bh[2 * h], bh[2 * h + 1]);
            }
        }
    }
}

__device__ __forceinline__ void issue_tile(uint32_t sm, uint32_t mb, int bid, int gq)
{
    int t = bid + (gq >> 3) * GRID_S;
    int chunk = gq & 7;                  // 8 chunks of K=64 per tile
    if (chunk == 0) {
        volatile int* p = &g_xprog[t >> 1];
        while (*p < 32) { }
    }
    int m0 = (t >> 1) << 7;
    int nb = (t & 1) << 8;
    int st = gq & (NSTG_S - 1);
    issue128(sm + st * STG_S, mb + 8 * st, m0, nb, chunk);
}

__global__ void __launch_bounds__(256, 1)
bulk_scores(const float* __restrict__ we)
{
    extern __shared__ char smc[];
    uint32_t sm = smem_u32(smc);
    int tid = threadIdx.x, lane = tid & 31, wid = tid >> 5;
    int wm = (wid >> 2) * 64, wn = (wid & 3) * 64;
    int wx = wid & 3;
    int bid = blockIdx.x;
    uint32_t mb  = sm + MB_S;                 // 4 full mbars
    uint32_t mbe = sm + MB_S + 8 * NSTG_S;    // 4 empty mbars (count 8)

    float* we_s  = (float*)(smc + TAB_S);
    float* cbbuf = we_s + 512;
    float* part  = cbbuf + 512;

    we_s[tid]       = we[tid];
    we_s[tid + 256] = we[tid + 256];

    int nt_cta = (NTILES - bid + GRID_S - 1) / GRID_S;
    int total = nt_cta * 8;

    if (tid == 0) {
        for (int s = 0; s < NSTG_S; s++) { MBAR_INIT(mb + 8 * s, 1); MBAR_INIT(mbe + 8 * s, 8); }
    }
    __syncthreads();
    if (tid == 0) {
        FENCE_ASYNC();
        for (int s = 0; s < NSTG_S && s < total; s++) issue_tile(sm, mb, bid, s);
    }

    float acc[4][8][4] = {};
    for (int gq = 0; gq < total; ++gq) {
        int tt = gq >> 3;
        int t  = bid + tt * GRID_S;
        int st = gq & (NSTG_S - 1);
        uint32_t ph = (uint32_t)((gq >> 2) & 1);   // gq / NSTG_S parity
        if ((gq & 7) == 0) {
            int bidx = t >> 2;
            int nb   = (t & 1) << 8;
            cbbuf[(tt & 1) * 256 + tid] = g_sProj[bidx * 512 + nb + tid];
        }
        mbar_wait(mb + 8 * st, ph);
        cchunk128(sm + st * STG_S, lane, wm, wn, acc);
        if (lane == 0) MBAR_ARRIVE(mbe + 8 * st);
        if (tid == 0 && gq + NSTG_S < total) {
            mbar_wait(mbe + 8 * st, ph);
            FENCE_ASYNC();
            issue_tile(sm, mb, bid, gq + NSTG_S);
        }
        if ((gq & 7) == 7) {
            __syncthreads();
            int m0 = (t >> 1) << 7;
            int nb = (t & 1) << 8;
            float* cb = cbbuf + (tt & 1) * 256;
            #pragma unroll
            for (int mt = 0; mt < 4; ++mt) {
                float s1 = 0.f, s2 = 0.f;
                #pragma unroll
                for (int ntc = 0; ntc < 8; ++ntc) {
                    int n = wn + ntc * 8 + 2 * (lane & 3);
                    float c0 = cb[n], c1 = cb[n + 1];
                    float w0 = we_s[nb + n], w1 = we_s[nb + n + 1];
                    s1 += tanh_fast(acc[mt][ntc][0] + c0) * w0 + tanh_fast(acc[mt][ntc][1] + c1) * w1;
                    s2 += tanh_fast(acc[mt][ntc][2] + c0) * w0 + tanh_fast(acc[mt][ntc][3] + c1) * w1;
                    acc[mt][ntc][0] = 0.f; acc[mt][ntc][1] = 0.f;
                    acc[mt][ntc][2] = 0.f; acc[mt][ntc][3] = 0.f;
                }
                s1 += __shfl_xor_sync(0xffffffffu, s1, 1); s1 += __shfl_xor_sync(0xffffffffu, s1, 2);
                s2 += __shfl_xor_sync(0xffffffffu, s2, 1); s2 += __shfl_xor_sync(0xffffffffu, s2, 2);
                if ((lane & 3) == 0) {
                    int rl = wm + mt * 16 + (lane >> 2);
                    part[wx * 128 + rl]     = s1;
                    part[wx * 128 + rl + 8] = s2;
                }
            }
            __syncthreads();
            if (tid < 128)
                g_spart[(t & 1) * 65536 + m0 + tid] =
                    part[tid] + part[128 + tid] + part[256 + tid] + part[384 + tid];
            __syncthreads();
        }
    }
}

// ---------------- fused softmax + context + cc ----------------
__global__ void softmax_ctx_cc(const float* __restrict__ emb,
                               const int* __restrict__ yPrev)
{
    int b = blockIdx.x, t = threadIdx.x;
    __shared__ float al[T_];
    __shared__ float red[T_];
    float v = g_spart[b * 256 + t] + g_spart[65536 + b * 256 + t];
    red[t] = v; __syncthreads();
    for (int s = 128; s; s >>= 1) { if (t < s) red[t] = fmaxf(red[t], red[t + s]); __syncthreads(); }
    float mx = red[0]; __syncthreads();
    float e = expf(v - mx);
    red[t] = e; __syncthreads();
    for (int s = 128; s; s >>= 1) { if (t < s) red[t] += red[t + s]; __syncthreads(); }
    al[t] = e / red[0];
    __syncthreads();

    float c0 = 0.f, c1 = 0.f;
    #pragma unroll 4
    for (int tt = 0; tt < 256; ++tt) {
        float a = al[tt];
        float2 xv = load_pair_tiled(g_x_t, 65536, b * 256 + tt, 2 * t);
        c0 += a * xv.x; c1 += a * xv.y;
    }
    store_pair_tiled(g_cc_t, 256, b, 512 + 2 * t, c0, c1);

    int y = yPrev[b];
    float2 ev = *(const float2*)(emb + (size_t)y * 512 + 2 * t);
    store_pair_tiled(g_cc_t, 256, b, 2 * t, ev.x, ev.y);
}

// ---------------- GRU elementwise ----------------
__global__ void gru_kernel(const float* __restrict__ s, float* __restrict__ h_out)
{
    int b = blockIdx.x, t = threadIdx.x;
    float hv[2];
    #pragma unroll
    for (int q = 0; q < 2; ++q) {
        int j = 2 * t + q;
        float ir = g_gi[b * 1536 + j];
        float iz = g_gi[b * 1536 + 512 + j];
        float in_ = g_gi[b * 1536 + 1024 + j];
        float hr = g_gh[b * 1536 + j];
        float hz = g_gh[b * 1536 + 512 + j];
        float hn = g_gh[b * 1536 + 1024 + j];
        float r = 1.f / (1.f + expf(-(ir + hr)));
        float z = 1.f / (1.f + expf(-(iz + hz)));
        float n = tanhf(in_ + r * hn);
        hv[q] = (1.f - z) * n + z * s[b * 512 + j];
        if (h_out) h_out[b * 512 + j] = hv[q];
    }
    store_pair_tiled(g_h_t, 256, b, 2 * t, hv[0], hv[1]);
}

// ======================================================================
extern "C" void kernel_launch(void* const* d_in, const int* in_sizes, int n_in,
                              void* d_out, int out_size)
{
    const float* x     = (const float*)d_in[0];
    const float* sPrev = (const float*)d_in[1];
    const int*   yPrev = (const int*)  d_in[2];
    const float* xe_w  = (const float*)d_in[3];
    const float* xe_b  = (const float*)d_in[4];
    const float* se_w  = (const float*)d_in[5];
    const float* se_b  = (const float*)d_in[6];
    const float* we_w  = (const float*)d_in[7];
    const float* emb   = (const float*)d_in[9];
    const float* w_ih  = (const float*)d_in[10];
    const float* w_hh  = (const float*)d_in[11];
    const float* b_ih  = (const float*)d_in[12];
    const float* b_hh  = (const float*)d_in[13];
    const float* fc_w  = (const float*)d_in[14];
    const float* fc_b  = (const float*)d_in[15];

    float* out = (float*)d_out;
    float* h_out = (out_size >= B_ * YD_ + B_ * 512) ? out + (size_t)B_ * YD_ : nullptr;

    float *sProj_p, *gi_p, *gh_p, *cbias_p;
    cudaGetSymbolAddress((void**)&sProj_p, g_sProj);
    cudaGetSymbolAddress((void**)&gi_p, g_gi);
    cudaGetSymbolAddress((void**)&gh_p, g_gh);
    cudaGetSymbolAddress((void**)&cbias_p, g_cbias);
    __half *s_t, *cc_t, *h_t, *se_t, *hh_t, *ih_t, *fc_t;
    cudaGetSymbolAddress((void**)&s_t,  g_s_t);
    cudaGetSymbolAddress((void**)&cc_t, g_cc_t);
    cudaGetSymbolAddress((void**)&h_t,  g_h_t);
    cudaGetSymbolAddress((void**)&se_t, g_se_t);
    cudaGetSymbolAddress((void**)&hh_t, g_hh_t);
    cudaGetSymbolAddress((void**)&ih_t, g_ih_t);
    cudaGetSymbolAddress((void**)&fc_t, g_fc_t);

    static cudaStream_t s2 = nullptr;
    static cudaEvent_t evFork = nullptr, evW = nullptr, evGH = nullptr;
    if (!s2) {
        cudaFuncSetAttribute(bulk_scores,      cudaFuncAttributeMaxDynamicSharedMemorySize, SMEM_S);
        cudaFuncSetAttribute(bulk_gemm<false>, cudaFuncAttributeMaxDynamicSharedMemorySize, SMEM_G);
        cudaFuncSetAttribute(bulk_gemm<true>,  cudaFuncAttributeMaxDynamicSharedMemorySize, SMEM_G);
        cudaStreamCreateWithFlags(&s2, cudaStreamNonBlocking);
        cudaEventCreateWithFlags(&evFork, cudaEventDisableTiming);
        cudaEventCreateWithFlags(&evW, cudaEventDisableTiming);
        cudaEventCreateWithFlags(&evGH, cudaEventDisableTiming);
    }

    // progress counters must be zero before split_x increments them
    zero_prog<<<2, 256>>>();

    // ---- capture fork ----
    cudaEventRecord(evFork, 0);
    cudaStreamWaitEvent(s2, evFork, 0);

    // ---- stream 2: x split (publishes g_xprog) ----
    split_x<<<16384, 256, 0, s2>>>(x);

    // ---- capture stream: s split, weight splits (+ cbias tail) ----
    split_gen<<<64, 256>>>(sPrev, s_t, 256, 512, 256 * 64);
    split_weights<<<(Q_TOT + 512 + 255) / 256, 256>>>(xe_w, se_w, w_hh, w_ih, fc_w, se_b, xe_b);
    cudaEventRecord(evW, 0);

    // gh on s2
    cudaStreamWaitEvent(s2, evW, 0);
    bulk_gemm<false><<<dim3(12, 4), 256, SMEM_G, s2>>>(s_t, 256, hh_t, 1536, b_hh, gh_p, 1536, 512);
    cudaEventRecord(evGH, s2);

    // ---- main chain (scores self-synchronizes against split_x via g_xprog) ----
    bulk_gemm<false><<<dim3(4, 4), 256, SMEM_G>>>(s_t, 256, se_t, 512, cbias_p, sProj_p, 512, 512);
    bulk_scores<<<GRID_S, 256, SMEM_S>>>(we_w);
    softmax_ctx_cc<<<256, 256>>>(emb, yPrev);
    bulk_gemm<false><<<dim3(12, 4), 256, SMEM_G>>>(cc_t, 256, ih_t, 1536, b_ih, gi_p, 1536, 1024);
    cudaStreamWaitEvent(0, evGH, 0);
    gru_kernel<<<256, 256>>>(sPrev, h_out);
    bulk_gemm<true><<<dim3(52, 4), 256, SMEM_G>>>(h_t, 256, fc_t, 6656, fc_b, out, 6625, 512);
}